// round 6
// baseline (speedup 1.0000x reference)
#include <cuda_runtime.h>
#include <cuda_bf16.h>
#include <math.h>

// ---- model dims ----
#define Tt   512
#define Hh   768
#define Ll   4
#define NHh  12
#define NKVv 4
#define HDd  64
#define Ee   64
#define Ff   192
#define KK   8
#define Vv   32000
#define REP  3   // NH / NKV
#define MAXTILES 128

// ---- fp32 scratch ----
__device__ float g_x[Tt*Hh];
__device__ float g_q[Tt*NHh*HDd];
__device__ float g_k[Tt*NKVv*HDd];
__device__ float g_v[Tt*NKVv*HDd];
__device__ float g_scores[(size_t)NHh*Tt*Tt];
__device__ float g_probs[Ll*Tt*Ee];
__device__ int   g_sel[Ll*Tt*KK];
__device__ float g_topw[Tt*KK];
__device__ int   g_cnt[Ee];
__device__ int   g_off[Ee+1];
__device__ int   g_pairs[Tt*KK];
__device__ int   g_ntiles;
__device__ int   g_tile_e[MAXTILES];
__device__ int   g_tile_base[MAXTILES];
__device__ int   g_tile_rows[MAXTILES];
__device__ float g_actg[Tt*KK*Ff];
__device__ float g_actu[Tt*KK*Ff];
__device__ float g_slotout[Tt*KK*Hh];
__device__ float g_nll[Tt];
__device__ float g_logits_fb[(size_t)Tt*Vv];

// ---- packed bf16 hi/lo word arrays for ACTIVATIONS only ----
__device__ __align__(16) unsigned g_xnh[Tt*384],  g_xnl[Tt*384];
__device__ __align__(16) unsigned g_qh[Tt*384],   g_ql[Tt*384];
__device__ __align__(16) unsigned g_kh[Tt*128],   g_kl[Tt*128];
__device__ __align__(16) unsigned g_sph[(size_t)NHh*Tt*256], g_spl[(size_t)NHh*Tt*256];
__device__ __align__(16) unsigned g_ath[Tt*384],  g_atl[Tt*384];
__device__ __align__(16) unsigned g_acth[Tt*KK*96], g_actl[Tt*KK*96];

// ------------------------------------------------------------------
__device__ __forceinline__ unsigned prmt_hi(unsigned a, unsigned b){
    unsigned d; asm("prmt.b32 %0,%1,%2,0x7632;" : "=r"(d) : "r"(a), "r"(b)); return d;
}
__device__ __forceinline__ unsigned pack_bf16x2(float lo, float hi){
    unsigned d; asm("cvt.rn.bf16x2.f32 %0,%1,%2;" : "=r"(d) : "f"(hi), "f"(lo)); return d;
}
__device__ __forceinline__ void split_pair(float x0, float x1, unsigned &hi, unsigned &lo){
    unsigned u0 = __float_as_uint(x0), u1 = __float_as_uint(x1);
    hi = prmt_hi(u0, u1);
    float r0 = x0 - __uint_as_float(u0 & 0xffff0000u);
    float r1 = x1 - __uint_as_float(u1 & 0xffff0000u);
    lo = pack_bf16x2(r0, r1);
}

#define MMA_BF16(d, a, b) \
    asm volatile("mma.sync.aligned.m16n8k16.row.col.f32.bf16.bf16.f32 " \
                 "{%0,%1,%2,%3},{%4,%5,%6,%7},{%8,%9},{%0,%1,%2,%3};" \
                 : "+f"(d[0]),"+f"(d[1]),"+f"(d[2]),"+f"(d[3]) \
                 : "r"(a[0]),"r"(a[1]),"r"(a[2]),"r"(a[3]),"r"(b[0]),"r"(b[1]))

// GEMM core, bf16x3, block 128x64, 8 warps (4Mx2N), warp 32x32.
// A: packed hi/lo word arrays, rows via rowidx[] or arow0+r.
// B: BMODE 0 = packed [N,Kw] (Bph/Bpl, brow0) ; 1 = fp32 [N,K] rm (Bf, ldb, col0)
//    2 = fp32 [K,N] rm (Bf, ldb, col0).
// Software-pipelined: next k-step's gmem loads prefetched into regs during MMA.
template<int BMODE>
__device__ __forceinline__ void mm_acc2(
    const unsigned* __restrict__ Ah, const unsigned* __restrict__ Al,
    int ldaw, int arow0, const int* __restrict__ rowidx,
    const unsigned* __restrict__ Bph, const unsigned* __restrict__ Bpl,
    int ldbw, int brow0,
    const float* __restrict__ Bf, int ldb, int col0,
    int Kw,
    float acc[2][4][4],
    unsigned (*As_hi)[20], unsigned (*As_lo)[20],
    unsigned (*Bs_hi)[20], unsigned (*Bs_lo)[20])
{
    int tid  = threadIdx.x;
    int lane = tid & 31, warp = tid >> 5;
    int wm = warp & 3, wn = warp >> 2;
    int gq = lane >> 2, tg = lane & 3;

    // A loader
    int lr = tid >> 1, lw = (tid & 1)*8;
    int gr = rowidx ? rowidx[lr] : (arow0 + lr);
    const unsigned* aph = Ah + (size_t)gr*ldaw + lw;
    const unsigned* apl = Al + (size_t)gr*ldaw + lw;
    uint4 rah0, rah1, ral0, ral1;

    // B loader state
    int br0 = tid >> 2, bw0 = (tid & 3)*4;          // BMODE0/1 row & word
    const unsigned* bph = (BMODE == 0) ? (Bph + (size_t)(brow0+br0)*ldbw + bw0) : nullptr;
    const unsigned* bpl = (BMODE == 0) ? (Bpl + (size_t)(brow0+br0)*ldbw + bw0) : nullptr;
    uint4 rbh, rbl;
    float4 rf0, rf1;                                 // BMODE1
    int bn2 = tid & 63, bk2 = (tid >> 6)*8;          // BMODE2
    float rf[8];

    // prologue: load k-step 0
    rah0 = *(const uint4*)(aph);
    rah1 = *(const uint4*)(aph + 4);
    ral0 = *(const uint4*)(apl);
    ral1 = *(const uint4*)(apl + 4);
    if (BMODE == 0){ rbh = *(const uint4*)(bph); rbl = *(const uint4*)(bpl); }
    else if (BMODE == 1){
        const float* p = Bf + (size_t)(col0+br0)*ldb + bw0*2;
        rf0 = *(const float4*)p; rf1 = *(const float4*)(p+4);
    } else if (BMODE == 2){
        const float* p = Bf + (size_t)bk2*ldb + col0 + bn2;
        #pragma unroll
        for (int j = 0; j < 8; j++) rf[j] = p[(size_t)j*ldb];
    }

    for (int k0w = 0; k0w < Kw; k0w += 16){
        __syncthreads();
        // regs -> smem
        *(uint4*)&As_hi[lr][lw]   = rah0;
        *(uint4*)&As_hi[lr][lw+4] = rah1;
        *(uint4*)&As_lo[lr][lw]   = ral0;
        *(uint4*)&As_lo[lr][lw+4] = ral1;
        if (BMODE == 0){
            *(uint4*)&Bs_hi[br0][bw0] = rbh;
            *(uint4*)&Bs_lo[br0][bw0] = rbl;
        } else if (BMODE == 1){
            unsigned h0,l0,h1,l1,h2,l2,h3,l3;
            split_pair(rf0.x, rf0.y, h0,l0); split_pair(rf0.z, rf0.w, h1,l1);
            split_pair(rf1.x, rf1.y, h2,l2); split_pair(rf1.z, rf1.w, h3,l3);
            *(uint4*)&Bs_hi[br0][bw0] = make_uint4(h0,h1,h2,h3);
            *(uint4*)&Bs_lo[br0][bw0] = make_uint4(l0,l1,l2,l3);
        } else {
            unsigned h[4], l[4];
            #pragma unroll
            for (int j = 0; j < 4; j++) split_pair(rf[2*j], rf[2*j+1], h[j], l[j]);
            *(uint4*)&Bs_hi[bn2][bk2>>1] = make_uint4(h[0],h[1],h[2],h[3]);
            *(uint4*)&Bs_lo[bn2][bk2>>1] = make_uint4(l[0],l[1],l[2],l[3]);
        }
        __syncthreads();

        // prefetch next k-step into regs (overlaps with MMAs below)
        if (k0w + 16 < Kw){
            int nk = k0w + 16;
            rah0 = *(const uint4*)(aph + nk);
            rah1 = *(const uint4*)(aph + nk + 4);
            ral0 = *(const uint4*)(apl + nk);
            ral1 = *(const uint4*)(apl + nk + 4);
            if (BMODE == 0){ rbh = *(const uint4*)(bph + nk); rbl = *(const uint4*)(bpl + nk); }
            else if (BMODE == 1){
                const float* p = Bf + (size_t)(col0+br0)*ldb + (nk + bw0)*2;
                rf0 = *(const float4*)p; rf1 = *(const float4*)(p+4);
            } else if (BMODE == 2){
                const float* p = Bf + (size_t)(2*nk + bk2)*ldb + col0 + bn2;
                #pragma unroll
                for (int j = 0; j < 8; j++) rf[j] = p[(size_t)j*ldb];
            }
        }

        #pragma unroll
        for (int s = 0; s < 2; s++){
            unsigned ah[2][4], al[2][4], bh[4][2], bl[4][2];
            int kw = 8*s + tg;
            #pragma unroll
            for (int mt = 0; mt < 2; mt++){
                int rb = wm*32 + mt*16 + gq;
                ah[mt][0] = As_hi[rb][kw];    ah[mt][1] = As_hi[rb+8][kw];
                ah[mt][2] = As_hi[rb][kw+4];  ah[mt][3] = As_hi[rb+8][kw+4];
                al[mt][0] = As_lo[rb][kw];    al[mt][1] = As_lo[rb+8][kw];
                al[mt][2] = As_lo[rb][kw+4];  al[mt][3] = As_lo[rb+8][kw+4];
            }
            #pragma unroll
            for (int nt = 0; nt < 4; nt++){
                int nb = wn*32 + nt*8 + gq;
                bh[nt][0] = Bs_hi[nb][kw]; bh[nt][1] = Bs_hi[nb][kw+4];
                bl[nt][0] = Bs_lo[nb][kw]; bl[nt][1] = Bs_lo[nb][kw+4];
            }
            #pragma unroll
            for (int mt = 0; mt < 2; mt++)
                #pragma unroll
                for (int nt = 0; nt < 4; nt++){
                    MMA_BF16(acc[mt][nt], ah[mt], bh[nt]);
                    MMA_BF16(acc[mt][nt], al[mt], bh[nt]);
                    MMA_BF16(acc[mt][nt], ah[mt], bl[nt]);
                }
        }
    }
}

#define MM_PROLOGUE() \
    __shared__ __align__(16) unsigned As_hi[128][20], As_lo[128][20]; \
    __shared__ __align__(16) unsigned Bs_hi[64][20],  Bs_lo[64][20]; \
    float acc[2][4][4]; \
    _Pragma("unroll") \
    for (int i = 0; i < 2; i++) \
        _Pragma("unroll") \
        for (int j = 0; j < 4; j++) \
            _Pragma("unroll") \
            for (int l = 0; l < 4; l++) acc[i][j][l] = 0.f;

__device__ __forceinline__ void epi_f32(float* C, int ldc, int row0, int col0,
                                        int doacc, float acc[2][4][4]){
    int tid = threadIdx.x, lane = tid & 31, warp = tid >> 5;
    int wm = warp & 3, wn = warp >> 2;
    int gq = lane >> 2, tg = lane & 3;
    #pragma unroll
    for (int mt = 0; mt < 2; mt++){
        int r0 = row0 + wm*32 + mt*16 + gq;
        #pragma unroll
        for (int nt = 0; nt < 4; nt++){
            int c0 = col0 + wn*32 + nt*8 + tg*2;
            float* p0 = &C[(size_t)r0*ldc + c0];
            float* p1 = &C[(size_t)(r0+8)*ldc + c0];
            if (doacc){
                p0[0] += acc[mt][nt][0]; p0[1] += acc[mt][nt][1];
                p1[0] += acc[mt][nt][2]; p1[1] += acc[mt][nt][3];
            } else {
                p0[0] = acc[mt][nt][0]; p0[1] = acc[mt][nt][1];
                p1[0] = acc[mt][nt][2]; p1[1] = acc[mt][nt][3];
            }
        }
    }
}

// ---- GEMM kernels ----
__global__ __launch_bounds__(256, 2)
void k_qkv(const float* __restrict__ Wq, const float* __restrict__ Wk,
           const float* __restrict__ Wv){
    MM_PROLOGUE();
    int bx = blockIdx.x, row0 = blockIdx.y*128;
    if (bx < 12){
        mm_acc2<2>(g_xnh, g_xnl, 384, row0, nullptr, nullptr, nullptr, 0, 0,
                   Wq, 768, bx*64, 384, acc, As_hi, As_lo, Bs_hi, Bs_lo);
        epi_f32(g_q, 768, row0, bx*64, 0, acc);
    } else if (bx < 16){
        mm_acc2<2>(g_xnh, g_xnl, 384, row0, nullptr, nullptr, nullptr, 0, 0,
                   Wk, 256, (bx-12)*64, 384, acc, As_hi, As_lo, Bs_hi, Bs_lo);
        epi_f32(g_k, 256, row0, (bx-12)*64, 0, acc);
    } else {
        mm_acc2<2>(g_xnh, g_xnl, 384, row0, nullptr, nullptr, nullptr, 0, 0,
                   Wv, 256, (bx-16)*64, 384, acc, As_hi, As_lo, Bs_hi, Bs_lo);
        epi_f32(g_v, 256, row0, (bx-16)*64, 0, acc);
    }
}

__global__ __launch_bounds__(256, 2)
void k_scores(){
    int h = blockIdx.z;
    if ((int)blockIdx.x >= 2*(int)blockIdx.y + 2) return;
    MM_PROLOGUE();
    int row0 = blockIdx.y*128, col0 = blockIdx.x*64;
    mm_acc2<0>(g_qh + h*32, g_ql + h*32, 384, row0, nullptr,
               g_kh + (h/REP)*32, g_kl + (h/REP)*32, 128, col0,
               nullptr, 0, 0, 32, acc, As_hi, As_lo, Bs_hi, Bs_lo);
    epi_f32(g_scores + (size_t)h*Tt*Tt, Tt, row0, col0, 0, acc);
}

__global__ __launch_bounds__(256, 2)
void k_pv(){
    int h = blockIdx.z;
    MM_PROLOGUE();
    int row0 = blockIdx.y*128;
    mm_acc2<2>(g_sph + (size_t)h*Tt*256, g_spl + (size_t)h*Tt*256, 256, row0, nullptr,
               nullptr, nullptr, 0, 0,
               g_v, 256, (h/REP)*64, 256, acc, As_hi, As_lo, Bs_hi, Bs_lo);
    int tid = threadIdx.x, lane = tid & 31, warp = tid >> 5;
    int wm = warp & 3, wn = warp >> 2;
    int gq = lane >> 2, tg = lane & 3;
    #pragma unroll
    for (int mt = 0; mt < 2; mt++){
        int r0 = row0 + wm*32 + mt*16 + gq;
        #pragma unroll
        for (int nt = 0; nt < 4; nt++){
            int wrd = h*32 + wn*16 + nt*4 + tg;
            unsigned hi, lo;
            split_pair(acc[mt][nt][0], acc[mt][nt][1], hi, lo);
            g_ath[(size_t)r0*384 + wrd] = hi; g_atl[(size_t)r0*384 + wrd] = lo;
            split_pair(acc[mt][nt][2], acc[mt][nt][3], hi, lo);
            g_ath[(size_t)(r0+8)*384 + wrd] = hi; g_atl[(size_t)(r0+8)*384 + wrd] = lo;
        }
    }
}

__global__ __launch_bounds__(256, 2)
void k_wo(const float* __restrict__ Wo){
    MM_PROLOGUE();
    int row0 = blockIdx.y*128, col0 = blockIdx.x*64;
    mm_acc2<2>(g_ath, g_atl, 384, row0, nullptr, nullptr, nullptr, 0, 0,
               Wo, 768, col0, 384, acc, As_hi, As_lo, Bs_hi, Bs_lo);
    epi_f32(g_x, 768, row0, col0, 1, acc);
}

__global__ __launch_bounds__(256, 2)
void k_lmhead(const float* __restrict__ embed, float* __restrict__ logits){
    MM_PROLOGUE();
    int row0 = blockIdx.y*128, col0 = blockIdx.x*64;
    mm_acc2<1>(g_xnh, g_xnl, 384, row0, nullptr, nullptr, nullptr, 0, 0,
               embed, 768, col0, 384, acc, As_hi, As_lo, Bs_hi, Bs_lo);
    epi_f32(logits, Vv, row0, col0, 0, acc);
}

__global__ __launch_bounds__(256, 2)
void k_moe_up(const float* __restrict__ Wg, const float* __restrict__ Wu){
    int ti = blockIdx.y;
    if (ti >= g_ntiles) return;
    MM_PROLOGUE();
    __shared__ int rowidx[128];
    int e = g_tile_e[ti], base = g_tile_base[ti], rows = g_tile_rows[ti];
    int tid = threadIdx.x;
    if (tid < 128){
        int s = base + (tid < rows ? tid : rows-1);
        rowidx[tid] = g_pairs[s] >> 3;
    }
    __syncthreads();
    int colb = blockIdx.x*64;
    const float* W = (blockIdx.z ? Wu : Wg) + (size_t)e*Hh*Ff;
    mm_acc2<2>(g_xnh, g_xnl, 384, 0, rowidx, nullptr, nullptr, 0, 0,
               W, Ff, colb, 384, acc, As_hi, As_lo, Bs_hi, Bs_lo);
    float* out = blockIdx.z ? g_actu : g_actg;
    int lane = tid & 31, warp = tid >> 5;
    int wm = warp & 3, wn = warp >> 2;
    int gq = lane >> 2, tg = lane & 3;
    #pragma unroll
    for (int mt = 0; mt < 2; mt++){
        #pragma unroll
        for (int hf = 0; hf < 2; hf++){
            int r = wm*32 + mt*16 + gq + hf*8;
            if (r < rows){
                float* op = &out[(size_t)(base + r)*Ff + colb + wn*32 + tg*2];
                #pragma unroll
                for (int nt = 0; nt < 4; nt++){
                    op[nt*8    ] = acc[mt][nt][hf*2];
                    op[nt*8 + 1] = acc[mt][nt][hf*2 + 1];
                }
            }
        }
    }
}

__global__ void k_act(){
    int i = blockIdx.x*256 + threadIdx.x;   // words
    if (i >= Tt*KK*96) return;
    float g0 = g_actg[2*i], g1 = g_actg[2*i + 1];
    float u0 = g_actu[2*i], u1 = g_actu[2*i + 1];
    float a0 = g0/(1.f+expf(-g0))*u0;
    float a1 = g1/(1.f+expf(-g1))*u1;
    unsigned hi, lo; split_pair(a0, a1, hi, lo);
    g_acth[i] = hi; g_actl[i] = lo;
}

__global__ __launch_bounds__(256, 2)
void k_moe_down(const float* __restrict__ Wd){
    int ti = blockIdx.y;
    if (ti >= g_ntiles) return;
    MM_PROLOGUE();
    __shared__ int rowidx[128];
    int e = g_tile_e[ti], base = g_tile_base[ti], rows = g_tile_rows[ti];
    int tid = threadIdx.x;
    if (tid < 128)
        rowidx[tid] = base + (tid < rows ? tid : rows-1);
    __syncthreads();
    int colb = blockIdx.x*64;
    mm_acc2<2>(g_acth, g_actl, 96, 0, rowidx, nullptr, nullptr, 0, 0,
               Wd + (size_t)e*Ff*Hh, 768, colb, 96, acc, As_hi, As_lo, Bs_hi, Bs_lo);
    int lane = tid & 31, warp = tid >> 5;
    int wm = warp & 3, wn = warp >> 2;
    int gq = lane >> 2, tg = lane & 3;
    #pragma unroll
    for (int mt = 0; mt < 2; mt++){
        #pragma unroll
        for (int hf = 0; hf < 2; hf++){
            int r = wm*32 + mt*16 + gq + hf*8;
            if (r < rows){
                int pr = g_pairs[base + r];
                float w = g_topw[pr];
                float* op = &g_slotout[(size_t)pr*Hh + colb + wn*32 + tg*2];
                #pragma unroll
                for (int nt = 0; nt < 4; nt++){
                    op[nt*8    ] = w*acc[mt][nt][hf*2];
                    op[nt*8 + 1] = w*acc[mt][nt][hf*2 + 1];
                }
            }
        }
    }
}

// ------------------------------------------------------------------
__global__ void k_embed(const int* __restrict__ ids, const float* __restrict__ emb){
    int t = blockIdx.x;
    int id = ids[t];
    for (int h = threadIdx.x; h < Hh; h += blockDim.x)
        g_x[t*Hh + h] = emb[(size_t)id*Hh + h];
}

__global__ void k_rmsnorm(const float* __restrict__ w){
    int t = blockIdx.x; int tid = threadIdx.x;   // 256
    __shared__ float xs[Hh];
    __shared__ float red[256];
    float s = 0.f;
    #pragma unroll
    for (int c = 0; c < 3; c++){
        float v = g_x[t*Hh + tid + 256*c];
        xs[tid + 256*c] = v; s += v*v;
    }
    red[tid] = s; __syncthreads();
    for (int o = 128; o > 0; o >>= 1){ if (tid < o) red[tid] += red[tid+o]; __syncthreads(); }
    float r = rsqrtf(red[0] / (float)Hh + 1e-6f);
    __syncthreads();
    #pragma unroll
    for (int c = 0; c < 3; c++){
        int h = tid + 256*c;
        xs[h] = xs[h] * r * w[h];
    }
    __syncthreads();
    for (int wd = tid; wd < 384; wd += 256){
        unsigned hi, lo; split_pair(xs[2*wd], xs[2*wd+1], hi, lo);
        g_xnh[t*384 + wd] = hi; g_xnl[t*384 + wd] = lo;
    }
}

__global__ void k_fill(float* p, int n){
    int i = blockIdx.x*256 + threadIdx.x;
    if (i < n) p[i] = 0.f;
}

__global__ void k_rope2(){
    int t = blockIdx.x;
    int w = threadIdx.x >> 5, j = threadIdx.x & 31;
    const float* p = (w < 12) ? &g_q[t*Hh + w*HDd] : &g_k[t*(NKVv*HDd) + (w-12)*HDd];
    float inv = exp2f(-(float)(2*j) * (13.287712379549449f / 64.0f));
    float ang = (float)t * inv;
    float c = cosf(ang), s = sinf(ang);
    float x0 = p[j], x1 = p[j+32];
    float y0 = x0*c - x1*s;
    float y1 = x1*c + x0*s;
    unsigned full = 0xffffffffu;
    int m = j & 15;
    float sa = __shfl_sync(full, y0, 2*m);
    float sb = __shfl_sync(full, y0, 2*m + 1);
    float ta = __shfl_sync(full, y1, 2*m);
    float tb = __shfl_sync(full, y1, 2*m + 1);
    float f0 = (j < 16) ? sa : ta;
    float f1 = (j < 16) ? sb : tb;
    unsigned hi, lo; split_pair(f0, f1, hi, lo);
    if (w < 12){
        g_qh[t*384 + w*32 + j] = hi; g_ql[t*384 + w*32 + j] = lo;
    } else {
        g_kh[t*128 + (w-12)*32 + j] = hi; g_kl[t*128 + (w-12)*32 + j] = lo;
    }
}

__global__ void k_softmax(){
    int t = blockIdx.x, h = blockIdx.y, tid = threadIdx.x;   // 128 thr
    const float* row = g_scores + (size_t)h*Tt*Tt + (size_t)t*Tt;
    __shared__ float p[Tt];
    __shared__ float red[128];
    float m = -1e30f;
    for (int kk = tid; kk <= t; kk += 128){
        float v = row[kk]*0.125f;
        p[kk] = v; m = fmaxf(m, v);
    }
    red[tid] = m; __syncthreads();
    for (int o = 64; o > 0; o >>= 1){ if (tid < o) red[tid] = fmaxf(red[tid], red[tid+o]); __syncthreads(); }
    m = red[0]; __syncthreads();
    float s = 0.f;
    for (int kk = tid; kk <= t; kk += 128){
        float e = expf(p[kk] - m);
        p[kk] = e; s += e;
    }
    red[tid] = s; __syncthreads();
    for (int o = 64; o > 0; o >>= 1){ if (tid < o) red[tid] += red[tid+o]; __syncthreads(); }
    float inv = 1.0f / red[0];
    size_t obase = ((size_t)h*Tt + t)*256;
    for (int wd = tid; wd < 256; wd += 128){
        float f0 = (2*wd     <= t) ? p[2*wd]*inv     : 0.f;
        float f1 = (2*wd + 1 <= t) ? p[2*wd+1]*inv   : 0.f;
        unsigned hi, lo; split_pair(f0, f1, hi, lo);
        g_sph[obase + wd] = hi; g_spl[obase + wd] = lo;
    }
}

__global__ void k_norm_router(const float* __restrict__ w, const float* __restrict__ rw,
                              int layer){
    int t = blockIdx.x, tid = threadIdx.x;   // 256
    __shared__ float xs[Hh];
    __shared__ float red[256];
    __shared__ float lg[64];
    float loc[3]; float ss = 0.f;
    #pragma unroll
    for (int c = 0; c < 3; c++){
        float v = g_x[t*Hh + tid + 256*c];
        loc[c] = v; ss += v*v;
    }
    red[tid] = ss; __syncthreads();
    for (int o = 128; o > 0; o >>= 1){ if (tid < o) red[tid] += red[tid+o]; __syncthreads(); }
    float r = rsqrtf(red[0] / (float)Hh + 1e-6f);
    #pragma unroll
    for (int c = 0; c < 3; c++){
        int h = tid + 256*c;
        xs[h] = loc[c] * r * w[h];
    }
    __syncthreads();
    for (int wd = tid; wd < 384; wd += 256){
        unsigned hi, lo; split_pair(xs[2*wd], xs[2*wd+1], hi, lo);
        g_xnh[t*384 + wd] = hi; g_xnl[t*384 + wd] = lo;
    }
    if (tid < 64){
        float a0=0.f, a1=0.f, a2=0.f, a3=0.f;
        #pragma unroll 4
        for (int h = 0; h < Hh; h += 4){
            a0 += xs[h  ] * rw[(h  )*Ee + tid];
            a1 += xs[h+1] * rw[(h+1)*Ee + tid];
            a2 += xs[h+2] * rw[(h+2)*Ee + tid];
            a3 += xs[h+3] * rw[(h+3)*Ee + tid];
        }
        lg[tid] = (a0+a1) + (a2+a3);
    }
    __syncthreads();
    if (tid < 32){
        float v0 = lg[tid], v1 = lg[tid+32];
        float m = fmaxf(v0, v1);
        #pragma unroll
        for (int o = 16; o > 0; o >>= 1) m = fmaxf(m, __shfl_xor_sync(0xffffffffu, m, o));
        float e0 = expf(v0 - m), e1 = expf(v1 - m);
        float s = e0 + e1;
        #pragma unroll
        for (int o = 16; o > 0; o >>= 1) s += __shfl_xor_sync(0xffffffffu, s, o);
        float p0 = e0 / s, p1 = e1 / s;
        g_probs[((size_t)layer*Tt + t)*Ee + tid]      = p0;
        g_probs[((size_t)layer*Tt + t)*Ee + tid + 32] = p1;
        lg[tid] = p0; lg[tid+32] = p1;
        __syncwarp();
        float tv[KK]; int ti[KK]; float ws = 0.f;
        #pragma unroll
        for (int k = 0; k < KK; k++){
            float c0 = lg[tid], c1 = lg[tid+32];
            float bv; int bi;
            if (c0 >= c1){ bv = c0; bi = tid; } else { bv = c1; bi = tid+32; }
            #pragma unroll
            for (int o = 16; o > 0; o >>= 1){
                float ov = __shfl_xor_sync(0xffffffffu, bv, o);
                int   oi = __shfl_xor_sync(0xffffffffu, bi, o);
                if (ov > bv || (ov == bv && oi < bi)){ bv = ov; bi = oi; }
            }
            tv[k] = bv; ti[k] = bi; ws += bv;
            if (tid == 0) lg[bi] = -1.0f;
            __syncwarp();
        }
        if (tid == 0){
            float inv = 1.0f / ws;
            #pragma unroll
            for (int k = 0; k < KK; k++){
                g_sel[((size_t)layer*Tt + t)*KK + k] = ti[k];
                g_topw[t*KK + k] = tv[k] * inv;
            }
        }
    }
}

__global__ void k_countscatter(int layer){
    __shared__ int c[Ee], off[Ee+1], fill[Ee];
    int tid = threadIdx.x;   // 512
    if (tid < Ee) c[tid] = 0;
    __syncthreads();
    const int* sel = &g_sel[(size_t)layer*Tt*KK];
    for (int i = tid; i < Tt*KK; i += 512) atomicAdd(&c[sel[i]], 1);
    __syncthreads();
    if (tid == 0){
        int run = 0;
        for (int e = 0; e < Ee; e++){ off[e] = run; run += c[e]; }
        off[Ee] = run;
        int n = 0;
        for (int e = 0; e < Ee; e++){
            for (int b = 0; b < c[e]; b += 128){
                g_tile_e[n] = e;
                g_tile_base[n] = off[e] + b;
                g_tile_rows[n] = min(128, c[e] - b);
                n++;
            }
        }
        g_ntiles = n;
    }
    __syncthreads();
    if (tid < Ee){ g_cnt[tid] = c[tid]; g_off[tid] = off[tid]; fill[tid] = off[tid]; }
    if (tid == 0) g_off[Ee] = off[Ee];
    __syncthreads();
    for (int i = tid; i < Tt*KK; i += 512){
        int e = sel[i];
        int pos = atomicAdd(&fill[e], 1);
        g_pairs[pos] = i;
    }
}

__global__ void k_combine_norm(const float* __restrict__ w){
    int t = blockIdx.x, tid = threadIdx.x;   // 256
    __shared__ float xs[Hh];
    __shared__ float red[256];
    float ss = 0.f;
    #pragma unroll
    for (int c = 0; c < 3; c++){
        int h = tid + 256*c;
        float s = g_x[t*Hh + h];
        #pragma unroll
        for (int sl = 0; sl < KK; sl++)
            s += g_slotout[(size_t)(t*KK + sl)*Hh + h];
        g_x[t*Hh + h] = s;
        xs[h] = s; ss += s*s;
    }
    red[tid] = ss; __syncthreads();
    for (int o = 128; o > 0; o >>= 1){ if (tid < o) red[tid] += red[tid+o]; __syncthreads(); }
    float r = rsqrtf(red[0] / (float)Hh + 1e-6f);
    __syncthreads();
    #pragma unroll
    for (int c = 0; c < 3; c++){
        int h = tid + 256*c;
        xs[h] = xs[h] * r * w[h];
    }
    __syncthreads();
    for (int wd = tid; wd < 384; wd += 256){
        unsigned hi, lo; split_pair(xs[2*wd], xs[2*wd+1], hi, lo);
        g_xnh[t*384 + wd] = hi; g_xnl[t*384 + wd] = lo;
    }
}

__global__ void k_ce(const float* __restrict__ logits, const int* __restrict__ labels){
    int t = blockIdx.x, tid = threadIdx.x;   // 256
    const float* row = logits + (size_t)t*Vv;
    __shared__ float rm[256], rs[256];
    float m = -1e30f, s = 0.f;
    for (int v = tid; v < Vv; v += 256){
        float x = row[v];
        float nm = fmaxf(m, x);
        s = s*expf(m - nm) + expf(x - nm);
        m = nm;
    }
    rm[tid] = m; rs[tid] = s; __syncthreads();
    for (int o = 128; o > 0; o >>= 1){
        if (tid < o){
            float m2 = rm[tid+o], s2 = rs[tid+o];
            float nm = fmaxf(rm[tid], m2);
            rs[tid] = rs[tid]*expf(rm[tid]-nm) + s2*expf(m2-nm);
            rm[tid] = nm;
        }
        __syncthreads();
    }
    if (tid == 0){
        float lse = logf(rs[0]) + rm[0];
        int lbl = labels[t];
        g_nll[t] = (lbl != -100) ? (lse - row[lbl < 0 ? 0 : lbl]) : 0.0f;
    }
}

__global__ void k_final(const int* __restrict__ labels, float* lossp){
    int tid = threadIdx.x;               // 64
    __shared__ int   ccnt[64];
    __shared__ float contrib[64];
    ccnt[tid] = 0; __syncthreads();
    for (int i = tid; i < Ll*Tt*KK; i += 64) atomicAdd(&ccnt[g_sel[i]], 1);
    float sp = 0.f;
    for (int r = 0; r < Ll*Tt; r++) sp += g_probs[(size_t)r*Ee + tid];
    __syncthreads();
    contrib[tid] = sp * (float)ccnt[tid];
    __syncthreads();
    if (tid == 0){
        float aux = 0.f;
        for (int e = 0; e < Ee; e++) aux += contrib[e];
        float NN = (float)(Ll*Tt);
        aux = aux / (NN*NN) * (float)Ee;
        float ce = 0.f; int valid = 0;
        for (int t = 0; t < Tt; t++){ ce += g_nll[t]; if (labels[t] != -100) valid++; }
        ce /= (valid > 0 ? (float)valid : 1.0f);
        if (lossp) *lossp = ce + 0.01f*aux;
    }
}

// ------------------------------------------------------------------
extern "C" void kernel_launch(void* const* d_in, const int* in_sizes, int n_in,
                              void* d_out, int out_size){
    const int*   ids    = (const int*)  d_in[0];
    const int*   labels = (const int*)  d_in[1];
    const float* embed  = (const float*)d_in[2];
    const float* ln1    = (const float*)d_in[3];
    const float* Wq     = (const float*)d_in[4];
    const float* Wk     = (const float*)d_in[5];
    const float* Wv     = (const float*)d_in[6];
    const float* Wo     = (const float*)d_in[7];
    const float* ln2    = (const float*)d_in[8];
    const float* rw     = (const float*)d_in[9];
    const float* Wg     = (const float*)d_in[10];
    const float* Wu     = (const float*)d_in[11];
    const float* Wd     = (const float*)d_in[12];
    const float* fnw    = (const float*)d_in[13];

    float *fbp, *nllp;
    cudaGetSymbolAddress((void**)&fbp, g_logits_fb);
    cudaGetSymbolAddress((void**)&nllp, g_nll);

    float* out = (float*)d_out;
    const size_t TV = (size_t)Tt * Vv;
    float* logits = ((size_t)out_size >= TV) ? out : fbp;
    float* lossp = nullptr;
    if ((size_t)out_size == TV + 1) lossp = out + TV;
    else if (out_size == 1)         lossp = out;

    k_embed<<<Tt, 256>>>(ids, embed);
    k_rmsnorm<<<Tt, 256>>>(ln1);
    // fillers so that launch index 5 (ncu -s 5 -c 1) is k_qkv
    k_fill<<<2, 256>>>(nllp, Tt);
    k_fill<<<2, 256>>>(nllp, Tt);
    k_fill<<<2, 256>>>(nllp, Tt);

    for (int i = 0; i < Ll; i++){
        k_qkv<<<dim3(20, Tt/128), 256>>>(Wq + (size_t)i*Hh*NHh*HDd,
                                         Wk + (size_t)i*Hh*NKVv*HDd,
                                         Wv + (size_t)i*Hh*NKVv*HDd);
        k_rope2<<<Tt, 512>>>();
        k_scores<<<dim3(Tt/64, Tt/128, NHh), 256>>>();
        k_softmax<<<dim3(Tt, NHh), 128>>>();
        k_pv<<<dim3(1, Tt/128, NHh), 256>>>();
        k_wo<<<dim3(Hh/64, Tt/128), 256>>>(Wo + (size_t)i*NHh*HDd*Hh);
        k_norm_router<<<Tt, 256>>>(ln2 + (size_t)i*Hh, rw + (size_t)i*Hh*Ee, i);
        k_countscatter<<<1, 512>>>(i);
        k_moe_up<<<dim3(3, 96, 2), 256>>>(Wg, Wu);
        k_act<<<1536, 256>>>();
        k_moe_down<<<dim3(12, 96), 256>>>(Wd);
        const float* wnext = (i < Ll-1) ? (ln1 + (size_t)(i+1)*Hh) : fnw;
        k_combine_norm<<<Tt, 256>>>(wnext);
    }

    k_lmhead<<<dim3(Vv/64, Tt/128), 256>>>(embed, logits);
    k_ce<<<Tt, 256>>>(logits, labels);
    k_final<<<1, 64>>>(labels, lossp);
}

// round 7
// speedup vs baseline: 1.4061x; 1.4061x over previous
#include <cuda_runtime.h>
#include <cuda_bf16.h>
#include <math.h>

// ---- model dims ----
#define Tt   512
#define Hh   768
#define Ll   4
#define NHh  12
#define NKVv 4
#define HDd  64
#define Ee   64
#define Ff   192
#define KK   8
#define Vv   32000
#define REP  3   // NH / NKV
#define MAXTILES 128

// ---- fp32 scratch ----
__device__ float g_x[Tt*Hh];
__device__ float g_q[Tt*NHh*HDd];
__device__ float g_k[Tt*NKVv*HDd];
__device__ float g_v[Tt*NKVv*HDd];
__device__ float g_scores[(size_t)NHh*Tt*Tt];
__device__ float g_probs[Ll*Tt*Ee];
__device__ int   g_sel[Ll*Tt*KK];
__device__ float g_topw[Tt*KK];
__device__ int   g_cnt[Ee];
__device__ int   g_off[Ee+1];
__device__ int   g_pairs[Tt*KK];
__device__ int   g_ntiles;
__device__ int   g_tile_e[MAXTILES];
__device__ int   g_tile_base[MAXTILES];
__device__ int   g_tile_rows[MAXTILES];
__device__ float g_actg[Tt*KK*Ff];
__device__ float g_actu[Tt*KK*Ff];
__device__ float g_slotout[Tt*KK*Hh];
__device__ float g_nll[Tt];
__device__ float g_logits_fb[(size_t)Tt*Vv];

// ---- packed bf16 hi/lo word arrays for ACTIVATIONS only ----
__device__ __align__(16) unsigned g_xnh[Tt*384],  g_xnl[Tt*384];
__device__ __align__(16) unsigned g_qh[Tt*384],   g_ql[Tt*384];
__device__ __align__(16) unsigned g_kh[Tt*128],   g_kl[Tt*128];
__device__ __align__(16) unsigned g_sph[(size_t)NHh*Tt*256], g_spl[(size_t)NHh*Tt*256];
__device__ __align__(16) unsigned g_ath[Tt*384],  g_atl[Tt*384];
__device__ __align__(16) unsigned g_acth[Tt*KK*96], g_actl[Tt*KK*96];

// ------------------------------------------------------------------
__device__ __forceinline__ unsigned prmt_hi(unsigned a, unsigned b){
    unsigned d; asm("prmt.b32 %0,%1,%2,0x7632;" : "=r"(d) : "r"(a), "r"(b)); return d;
}
__device__ __forceinline__ unsigned pack_bf16x2(float lo, float hi){
    unsigned d; asm("cvt.rn.bf16x2.f32 %0,%1,%2;" : "=r"(d) : "f"(hi), "f"(lo)); return d;
}
__device__ __forceinline__ void split_pair(float x0, float x1, unsigned &hi, unsigned &lo){
    unsigned u0 = __float_as_uint(x0), u1 = __float_as_uint(x1);
    hi = prmt_hi(u0, u1);
    float r0 = x0 - __uint_as_float(u0 & 0xffff0000u);
    float r1 = x1 - __uint_as_float(u1 & 0xffff0000u);
    lo = pack_bf16x2(r0, r1);
}

#define MMA_BF16(d, a, b) \
    asm volatile("mma.sync.aligned.m16n8k16.row.col.f32.bf16.bf16.f32 " \
                 "{%0,%1,%2,%3},{%4,%5,%6,%7},{%8,%9},{%0,%1,%2,%3};" \
                 : "+f"(d[0]),"+f"(d[1]),"+f"(d[2]),"+f"(d[3]) \
                 : "r"(a[0]),"r"(a[1]),"r"(a[2]),"r"(a[3]),"r"(b[0]),"r"(b[1]))

// cp.async helpers (16B)
__device__ __forceinline__ void cp16(void* s, const void* g){
    unsigned sa = (unsigned)__cvta_generic_to_shared(s);
    asm volatile("cp.async.cg.shared.global [%0], [%1], 16;\n" :: "r"(sa), "l"(g));
}
#define CP_COMMIT() asm volatile("cp.async.commit_group;\n" ::: "memory")
#define CP_WAIT(n)  asm volatile("cp.async.wait_group %0;\n" :: "n"(n) : "memory")

// ------------------------------------------------------------------
// cp.async double-buffered GEMM core. Block 128x64, 8 warps (4Mx2N), warp 32x32.
// k-step = 16 K (8 packed words). A: packed hi/lo words [rows, Kw], rows via
// rowidx[] or arow0+r. B: BMODE 0 = packed [N,Kw]; 1 = fp32 [N,K] rm;
// 2 = fp32 [K,N] rm. col0 = N-offset of this block's 64-wide tile.
template<int BMODE>
__device__ __forceinline__ void mm_async(
    const unsigned* __restrict__ Ah, const unsigned* __restrict__ Al,
    int ldaw, int arow0, const int* __restrict__ rowidx,
    const unsigned* __restrict__ Bph, const unsigned* __restrict__ Bpl, int ldbw,
    const float* __restrict__ Bf, int ldb,
    int col0, int Kw, float acc[2][4][4])
{
    __shared__ __align__(16) unsigned As_h[2][128][12];
    __shared__ __align__(16) unsigned As_l[2][128][12];
    __shared__ __align__(16) unsigned Bs[2][1536];

    int tid  = threadIdx.x;
    int lane = tid & 31, warp = tid >> 5;
    int wm = warp & 3, wn = warp >> 2;
    int gq = lane >> 2, tg = lane & 3;

    // A stage assignment: 128 rows x 2 chunks (of 4 words) per array
    int ar = tid >> 1, ac = (tid & 1)*4;
    int gr = rowidx ? rowidx[ar] : (arow0 + ar);
    const unsigned* gAh = Ah + (size_t)gr*ldaw + ac;
    const unsigned* gAl = Al + (size_t)gr*ldaw + ac;

    auto stage = [&](int ks, int buf){
        cp16(&As_h[buf][ar][ac], gAh + ks*8);
        cp16(&As_l[buf][ar][ac], gAl + ks*8);
        if (BMODE == 0){
            int a = tid >> 7, rem = tid & 127;
            int row = rem >> 1, ch = (rem & 1)*4;
            const unsigned* src = (a ? Bpl : Bph) + (size_t)(col0+row)*ldbw + ks*8 + ch;
            cp16(&Bs[buf][a*768 + row*12 + ch], src);
        } else if (BMODE == 1){
            int row = tid >> 2, ch = (tid & 3)*4;
            const float* src = Bf + (size_t)(col0+row)*ldb + ks*16 + ch;
            cp16(&Bs[buf][row*20 + ch], src);
        } else {
            int row = tid >> 4, ch = (tid & 15)*4;
            const float* src = Bf + (size_t)(ks*16 + row)*ldb + col0 + ch;
            cp16(&Bs[buf][row*68 + ch], src);
        }
    };

    int nst = Kw >> 3;
    stage(0, 0); CP_COMMIT();

    for (int ks = 0; ks < nst; ks++){
        int buf = ks & 1;
        if (ks + 1 < nst){ stage(ks+1, buf^1); CP_COMMIT(); CP_WAIT(1); }
        else             { CP_WAIT(0); }
        __syncthreads();

        unsigned ah[2][4], al[2][4], bh[4][2], bl[4][2];
        #pragma unroll
        for (int mt = 0; mt < 2; mt++){
            int rb = wm*32 + mt*16 + gq;
            ah[mt][0] = As_h[buf][rb][tg];     ah[mt][1] = As_h[buf][rb+8][tg];
            ah[mt][2] = As_h[buf][rb][tg+4];   ah[mt][3] = As_h[buf][rb+8][tg+4];
            al[mt][0] = As_l[buf][rb][tg];     al[mt][1] = As_l[buf][rb+8][tg];
            al[mt][2] = As_l[buf][rb][tg+4];   al[mt][3] = As_l[buf][rb+8][tg+4];
        }
        #pragma unroll
        for (int nt = 0; nt < 4; nt++){
            int nb = wn*32 + nt*8 + gq;
            if (BMODE == 0){
                bh[nt][0] = Bs[buf][nb*12 + tg];       bh[nt][1] = Bs[buf][nb*12 + tg+4];
                bl[nt][0] = Bs[buf][768 + nb*12 + tg]; bl[nt][1] = Bs[buf][768 + nb*12 + tg+4];
            } else if (BMODE == 1){
                const float* bp = (const float*)Bs[buf];
                float2 v0 = *(const float2*)&bp[nb*20 + 2*tg];
                float2 v1 = *(const float2*)&bp[nb*20 + 2*tg + 8];
                split_pair(v0.x, v0.y, bh[nt][0], bl[nt][0]);
                split_pair(v1.x, v1.y, bh[nt][1], bl[nt][1]);
            } else {
                const float* bp = (const float*)Bs[buf];
                split_pair(bp[(2*tg  )*68 + nb], bp[(2*tg+1)*68 + nb], bh[nt][0], bl[nt][0]);
                split_pair(bp[(2*tg+8)*68 + nb], bp[(2*tg+9)*68 + nb], bh[nt][1], bl[nt][1]);
            }
        }
        #pragma unroll
        for (int mt = 0; mt < 2; mt++)
            #pragma unroll
            for (int nt = 0; nt < 4; nt++){
                MMA_BF16(acc[mt][nt], ah[mt], bh[nt]);
                MMA_BF16(acc[mt][nt], al[mt], bh[nt]);
                MMA_BF16(acc[mt][nt], ah[mt], bl[nt]);
            }
        __syncthreads();
    }
}

#define MM_PROLOGUE() \
    float acc[2][4][4]; \
    _Pragma("unroll") \
    for (int i = 0; i < 2; i++) \
        _Pragma("unroll") \
        for (int j = 0; j < 4; j++) \
            _Pragma("unroll") \
            for (int l = 0; l < 4; l++) acc[i][j][l] = 0.f;

__device__ __forceinline__ void epi_f32(float* C, int ldc, int row0, int col0,
                                        int doacc, float acc[2][4][4]){
    int tid = threadIdx.x, lane = tid & 31, warp = tid >> 5;
    int wm = warp & 3, wn = warp >> 2;
    int gq = lane >> 2, tg = lane & 3;
    #pragma unroll
    for (int mt = 0; mt < 2; mt++){
        int r0 = row0 + wm*32 + mt*16 + gq;
        #pragma unroll
        for (int nt = 0; nt < 4; nt++){
            int c0 = col0 + wn*32 + nt*8 + tg*2;
            float* p0 = &C[(size_t)r0*ldc + c0];
            float* p1 = &C[(size_t)(r0+8)*ldc + c0];
            if (doacc){
                p0[0] += acc[mt][nt][0]; p0[1] += acc[mt][nt][1];
                p1[0] += acc[mt][nt][2]; p1[1] += acc[mt][nt][3];
            } else {
                p0[0] = acc[mt][nt][0]; p0[1] = acc[mt][nt][1];
                p1[0] = acc[mt][nt][2]; p1[1] = acc[mt][nt][3];
            }
        }
    }
}

// ---- GEMM kernels ----
__global__ __launch_bounds__(256, 2)
void k_qkv(const float* __restrict__ Wq, const float* __restrict__ Wk,
           const float* __restrict__ Wv){
    MM_PROLOGUE();
    int bx = blockIdx.x, row0 = blockIdx.y*128;
    if (bx < 12){
        mm_async<2>(g_xnh, g_xnl, 384, row0, nullptr, nullptr, nullptr, 0,
                    Wq, 768, bx*64, 384, acc);
        epi_f32(g_q, 768, row0, bx*64, 0, acc);
    } else if (bx < 16){
        mm_async<2>(g_xnh, g_xnl, 384, row0, nullptr, nullptr, nullptr, 0,
                    Wk, 256, (bx-12)*64, 384, acc);
        epi_f32(g_k, 256, row0, (bx-12)*64, 0, acc);
    } else {
        mm_async<2>(g_xnh, g_xnl, 384, row0, nullptr, nullptr, nullptr, 0,
                    Wv, 256, (bx-16)*64, 384, acc);
        epi_f32(g_v, 256, row0, (bx-16)*64, 0, acc);
    }
}

__global__ __launch_bounds__(256, 2)
void k_scores(){
    int h = blockIdx.z;
    if ((int)blockIdx.x >= 2*(int)blockIdx.y + 2) return;
    MM_PROLOGUE();
    int row0 = blockIdx.y*128, col0 = blockIdx.x*64;
    mm_async<0>(g_qh + h*32, g_ql + h*32, 384, row0, nullptr,
                g_kh + (h/REP)*32, g_kl + (h/REP)*32, 128,
                nullptr, 0, col0, 32, acc);
    epi_f32(g_scores + (size_t)h*Tt*Tt, Tt, row0, col0, 0, acc);
}

__global__ __launch_bounds__(256, 2)
void k_pv(){
    int h = blockIdx.z;
    MM_PROLOGUE();
    int row0 = blockIdx.y*128;
    mm_async<2>(g_sph + (size_t)h*Tt*256, g_spl + (size_t)h*Tt*256, 256, row0, nullptr,
                nullptr, nullptr, 0,
                g_v, 256, (h/REP)*64, 256, acc);
    int tid = threadIdx.x, lane = tid & 31, warp = tid >> 5;
    int wm = warp & 3, wn = warp >> 2;
    int gq = lane >> 2, tg = lane & 3;
    #pragma unroll
    for (int mt = 0; mt < 2; mt++){
        int r0 = row0 + wm*32 + mt*16 + gq;
        #pragma unroll
        for (int nt = 0; nt < 4; nt++){
            int wrd = h*32 + wn*16 + nt*4 + tg;
            unsigned hi, lo;
            split_pair(acc[mt][nt][0], acc[mt][nt][1], hi, lo);
            g_ath[(size_t)r0*384 + wrd] = hi; g_atl[(size_t)r0*384 + wrd] = lo;
            split_pair(acc[mt][nt][2], acc[mt][nt][3], hi, lo);
            g_ath[(size_t)(r0+8)*384 + wrd] = hi; g_atl[(size_t)(r0+8)*384 + wrd] = lo;
        }
    }
}

__global__ __launch_bounds__(256, 2)
void k_wo(const float* __restrict__ Wo){
    MM_PROLOGUE();
    int row0 = blockIdx.y*128, col0 = blockIdx.x*64;
    mm_async<2>(g_ath, g_atl, 384, row0, nullptr, nullptr, nullptr, 0,
                Wo, 768, col0, 384, acc);
    epi_f32(g_x, 768, row0, col0, 1, acc);
}

__global__ __launch_bounds__(256, 2)
void k_lmhead(const float* __restrict__ embed, float* __restrict__ logits){
    MM_PROLOGUE();
    int row0 = blockIdx.y*128, col0 = blockIdx.x*64;
    mm_async<1>(g_xnh, g_xnl, 384, row0, nullptr, nullptr, nullptr, 0,
                embed, 768, col0, 384, acc);
    epi_f32(logits, Vv, row0, col0, 0, acc);
}

__global__ __launch_bounds__(256, 2)
void k_moe_up(const float* __restrict__ Wg, const float* __restrict__ Wu){
    int ti = blockIdx.y;
    if (ti >= g_ntiles) return;
    MM_PROLOGUE();
    __shared__ int rowidx[128];
    int e = g_tile_e[ti], base = g_tile_base[ti], rows = g_tile_rows[ti];
    int tid = threadIdx.x;
    if (tid < 128){
        int s = base + (tid < rows ? tid : rows-1);
        rowidx[tid] = g_pairs[s] >> 3;
    }
    __syncthreads();
    int colb = blockIdx.x*64;
    const float* W = (blockIdx.z ? Wu : Wg) + (size_t)e*Hh*Ff;
    mm_async<2>(g_xnh, g_xnl, 384, 0, rowidx, nullptr, nullptr, 0,
                W, Ff, colb, 384, acc);
    float* out = blockIdx.z ? g_actu : g_actg;
    int lane = tid & 31, warp = tid >> 5;
    int wm = warp & 3, wn = warp >> 2;
    int gq = lane >> 2, tg = lane & 3;
    #pragma unroll
    for (int mt = 0; mt < 2; mt++){
        #pragma unroll
        for (int hf = 0; hf < 2; hf++){
            int r = wm*32 + mt*16 + gq + hf*8;
            if (r < rows){
                float* op = &out[(size_t)(base + r)*Ff + colb + wn*32 + tg*2];
                #pragma unroll
                for (int nt = 0; nt < 4; nt++){
                    op[nt*8    ] = acc[mt][nt][hf*2];
                    op[nt*8 + 1] = acc[mt][nt][hf*2 + 1];
                }
            }
        }
    }
}

__global__ void k_act(){
    int i = blockIdx.x*256 + threadIdx.x;   // words
    if (i >= Tt*KK*96) return;
    float g0 = g_actg[2*i], g1 = g_actg[2*i + 1];
    float u0 = g_actu[2*i], u1 = g_actu[2*i + 1];
    float a0 = g0/(1.f+expf(-g0))*u0;
    float a1 = g1/(1.f+expf(-g1))*u1;
    unsigned hi, lo; split_pair(a0, a1, hi, lo);
    g_acth[i] = hi; g_actl[i] = lo;
}

__global__ __launch_bounds__(256, 2)
void k_moe_down(const float* __restrict__ Wd){
    int ti = blockIdx.y;
    if (ti >= g_ntiles) return;
    MM_PROLOGUE();
    __shared__ int rowidx[128];
    int e = g_tile_e[ti], base = g_tile_base[ti], rows = g_tile_rows[ti];
    int tid = threadIdx.x;
    if (tid < 128)
        rowidx[tid] = base + (tid < rows ? tid : rows-1);
    __syncthreads();
    int colb = blockIdx.x*64;
    mm_async<2>(g_acth, g_actl, 96, 0, rowidx, nullptr, nullptr, 0,
                Wd + (size_t)e*Ff*Hh, 768, colb, 96, acc);
    int lane = tid & 31, warp = tid >> 5;
    int wm = warp & 3, wn = warp >> 2;
    int gq = lane >> 2, tg = lane & 3;
    #pragma unroll
    for (int mt = 0; mt < 2; mt++){
        #pragma unroll
        for (int hf = 0; hf < 2; hf++){
            int r = wm*32 + mt*16 + gq + hf*8;
            if (r < rows){
                int pr = g_pairs[base + r];
                float w = g_topw[pr];
                float* op = &g_slotout[(size_t)pr*Hh + colb + wn*32 + tg*2];
                #pragma unroll
                for (int nt = 0; nt < 4; nt++){
                    op[nt*8    ] = w*acc[mt][nt][hf*2];
                    op[nt*8 + 1] = w*acc[mt][nt][hf*2 + 1];
                }
            }
        }
    }
}

// ------------------------------------------------------------------
__global__ void k_embed(const int* __restrict__ ids, const float* __restrict__ emb){
    int t = blockIdx.x;
    int id = ids[t];
    for (int h = threadIdx.x; h < Hh; h += blockDim.x)
        g_x[t*Hh + h] = emb[(size_t)id*Hh + h];
}

__global__ void k_rmsnorm(const float* __restrict__ w){
    int t = blockIdx.x; int tid = threadIdx.x;   // 256
    __shared__ float xs[Hh];
    __shared__ float red[256];
    float s = 0.f;
    #pragma unroll
    for (int c = 0; c < 3; c++){
        float v = g_x[t*Hh + tid + 256*c];
        xs[tid + 256*c] = v; s += v*v;
    }
    red[tid] = s; __syncthreads();
    for (int o = 128; o > 0; o >>= 1){ if (tid < o) red[tid] += red[tid+o]; __syncthreads(); }
    float r = rsqrtf(red[0] / (float)Hh + 1e-6f);
    __syncthreads();
    #pragma unroll
    for (int c = 0; c < 3; c++){
        int h = tid + 256*c;
        xs[h] = xs[h] * r * w[h];
    }
    __syncthreads();
    for (int wd = tid; wd < 384; wd += 256){
        unsigned hi, lo; split_pair(xs[2*wd], xs[2*wd+1], hi, lo);
        g_xnh[t*384 + wd] = hi; g_xnl[t*384 + wd] = lo;
    }
}

__global__ void k_rope2(){
    int t = blockIdx.x;
    int w = threadIdx.x >> 5, j = threadIdx.x & 31;
    const float* p = (w < 12) ? &g_q[t*Hh + w*HDd] : &g_k[t*(NKVv*HDd) + (w-12)*HDd];
    float inv = exp2f(-(float)(2*j) * (13.287712379549449f / 64.0f));
    float ang = (float)t * inv;
    float c = cosf(ang), s = sinf(ang);
    float x0 = p[j], x1 = p[j+32];
    float y0 = x0*c - x1*s;
    float y1 = x1*c + x0*s;
    unsigned full = 0xffffffffu;
    int m = j & 15;
    float sa = __shfl_sync(full, y0, 2*m);
    float sb = __shfl_sync(full, y0, 2*m + 1);
    float ta = __shfl_sync(full, y1, 2*m);
    float tb = __shfl_sync(full, y1, 2*m + 1);
    float f0 = (j < 16) ? sa : ta;
    float f1 = (j < 16) ? sb : tb;
    unsigned hi, lo; split_pair(f0, f1, hi, lo);
    if (w < 12){
        g_qh[t*384 + w*32 + j] = hi; g_ql[t*384 + w*32 + j] = lo;
    } else {
        g_kh[t*128 + (w-12)*32 + j] = hi; g_kl[t*128 + (w-12)*32 + j] = lo;
    }
}

__global__ void k_softmax(){
    int t = blockIdx.x, h = blockIdx.y, tid = threadIdx.x;   // 128 thr
    const float* row = g_scores + (size_t)h*Tt*Tt + (size_t)t*Tt;
    __shared__ float p[Tt];
    __shared__ float red[128];
    float m = -1e30f;
    for (int kk = tid; kk <= t; kk += 128){
        float v = row[kk]*0.125f;
        p[kk] = v; m = fmaxf(m, v);
    }
    red[tid] = m; __syncthreads();
    for (int o = 64; o > 0; o >>= 1){ if (tid < o) red[tid] = fmaxf(red[tid], red[tid+o]); __syncthreads(); }
    m = red[0]; __syncthreads();
    float s = 0.f;
    for (int kk = tid; kk <= t; kk += 128){
        float e = expf(p[kk] - m);
        p[kk] = e; s += e;
    }
    red[tid] = s; __syncthreads();
    for (int o = 64; o > 0; o >>= 1){ if (tid < o) red[tid] += red[tid+o]; __syncthreads(); }
    float inv = 1.0f / red[0];
    size_t obase = ((size_t)h*Tt + t)*256;
    for (int wd = tid; wd < 256; wd += 128){
        float f0 = (2*wd     <= t) ? p[2*wd]*inv     : 0.f;
        float f1 = (2*wd + 1 <= t) ? p[2*wd+1]*inv   : 0.f;
        unsigned hi, lo; split_pair(f0, f1, hi, lo);
        g_sph[obase + wd] = hi; g_spl[obase + wd] = lo;
    }
}

__global__ void k_norm_router(const float* __restrict__ w, const float* __restrict__ rw,
                              int layer){
    int t = blockIdx.x, tid = threadIdx.x;   // 256
    __shared__ float xs[Hh];
    __shared__ float red[256];
    __shared__ float lg[64];
    float loc[3]; float ss = 0.f;
    #pragma unroll
    for (int c = 0; c < 3; c++){
        float v = g_x[t*Hh + tid + 256*c];
        loc[c] = v; ss += v*v;
    }
    red[tid] = ss; __syncthreads();
    for (int o = 128; o > 0; o >>= 1){ if (tid < o) red[tid] += red[tid+o]; __syncthreads(); }
    float r = rsqrtf(red[0] / (float)Hh + 1e-6f);
    #pragma unroll
    for (int c = 0; c < 3; c++){
        int h = tid + 256*c;
        xs[h] = loc[c] * r * w[h];
    }
    __syncthreads();
    for (int wd = tid; wd < 384; wd += 256){
        unsigned hi, lo; split_pair(xs[2*wd], xs[2*wd+1], hi, lo);
        g_xnh[t*384 + wd] = hi; g_xnl[t*384 + wd] = lo;
    }
    if (tid < 64){
        float a0=0.f, a1=0.f, a2=0.f, a3=0.f;
        #pragma unroll 4
        for (int h = 0; h < Hh; h += 4){
            a0 += xs[h  ] * rw[(h  )*Ee + tid];
            a1 += xs[h+1] * rw[(h+1)*Ee + tid];
            a2 += xs[h+2] * rw[(h+2)*Ee + tid];
            a3 += xs[h+3] * rw[(h+3)*Ee + tid];
        }
        lg[tid] = (a0+a1) + (a2+a3);
    }
    __syncthreads();
    if (tid < 32){
        float v0 = lg[tid], v1 = lg[tid+32];
        float m = fmaxf(v0, v1);
        #pragma unroll
        for (int o = 16; o > 0; o >>= 1) m = fmaxf(m, __shfl_xor_sync(0xffffffffu, m, o));
        float e0 = expf(v0 - m), e1 = expf(v1 - m);
        float s = e0 + e1;
        #pragma unroll
        for (int o = 16; o > 0; o >>= 1) s += __shfl_xor_sync(0xffffffffu, s, o);
        float p0 = e0 / s, p1 = e1 / s;
        g_probs[((size_t)layer*Tt + t)*Ee + tid]      = p0;
        g_probs[((size_t)layer*Tt + t)*Ee + tid + 32] = p1;
        lg[tid] = p0; lg[tid+32] = p1;
        __syncwarp();
        float tv[KK]; int ti[KK]; float ws = 0.f;
        #pragma unroll
        for (int k = 0; k < KK; k++){
            float c0 = lg[tid], c1 = lg[tid+32];
            float bv; int bi;
            if (c0 >= c1){ bv = c0; bi = tid; } else { bv = c1; bi = tid+32; }
            #pragma unroll
            for (int o = 16; o > 0; o >>= 1){
                float ov = __shfl_xor_sync(0xffffffffu, bv, o);
                int   oi = __shfl_xor_sync(0xffffffffu, bi, o);
                if (ov > bv || (ov == bv && oi < bi)){ bv = ov; bi = oi; }
            }
            tv[k] = bv; ti[k] = bi; ws += bv;
            if (tid == 0) lg[bi] = -1.0f;
            __syncwarp();
        }
        if (tid == 0){
            float inv = 1.0f / ws;
            #pragma unroll
            for (int k = 0; k < KK; k++){
                g_sel[((size_t)layer*Tt + t)*KK + k] = ti[k];
                g_topw[t*KK + k] = tv[k] * inv;
            }
        }
    }
}

__global__ void k_countscatter(int layer){
    __shared__ int c[Ee], off[Ee+1], fill[Ee];
    int tid = threadIdx.x;   // 512
    if (tid < Ee) c[tid] = 0;
    __syncthreads();
    const int* sel = &g_sel[(size_t)layer*Tt*KK];
    for (int i = tid; i < Tt*KK; i += 512) atomicAdd(&c[sel[i]], 1);
    __syncthreads();
    if (tid == 0){
        int run = 0;
        for (int e = 0; e < Ee; e++){ off[e] = run; run += c[e]; }
        off[Ee] = run;
        int n = 0;
        for (int e = 0; e < Ee; e++){
            for (int b = 0; b < c[e]; b += 128){
                g_tile_e[n] = e;
                g_tile_base[n] = off[e] + b;
                g_tile_rows[n] = min(128, c[e] - b);
                n++;
            }
        }
        g_ntiles = n;
    }
    __syncthreads();
    if (tid < Ee){ g_cnt[tid] = c[tid]; g_off[tid] = off[tid]; fill[tid] = off[tid]; }
    if (tid == 0) g_off[Ee] = off[Ee];
    __syncthreads();
    for (int i = tid; i < Tt*KK; i += 512){
        int e = sel[i];
        int pos = atomicAdd(&fill[e], 1);
        g_pairs[pos] = i;
    }
}

__global__ void k_combine_norm(const float* __restrict__ w){
    int t = blockIdx.x, tid = threadIdx.x;   // 256
    __shared__ float xs[Hh];
    __shared__ float red[256];
    float ss = 0.f;
    #pragma unroll
    for (int c = 0; c < 3; c++){
        int h = tid + 256*c;
        float s = g_x[t*Hh + h];
        #pragma unroll
        for (int sl = 0; sl < KK; sl++)
            s += g_slotout[(size_t)(t*KK + sl)*Hh + h];
        g_x[t*Hh + h] = s;
        xs[h] = s; ss += s*s;
    }
    red[tid] = ss; __syncthreads();
    for (int o = 128; o > 0; o >>= 1){ if (tid < o) red[tid] += red[tid+o]; __syncthreads(); }
    float r = rsqrtf(red[0] / (float)Hh + 1e-6f);
    __syncthreads();
    #pragma unroll
    for (int c = 0; c < 3; c++){
        int h = tid + 256*c;
        xs[h] = xs[h] * r * w[h];
    }
    __syncthreads();
    for (int wd = tid; wd < 384; wd += 256){
        unsigned hi, lo; split_pair(xs[2*wd], xs[2*wd+1], hi, lo);
        g_xnh[t*384 + wd] = hi; g_xnl[t*384 + wd] = lo;
    }
}

__global__ void k_ce(const float* __restrict__ logits, const int* __restrict__ labels){
    int t = blockIdx.x, tid = threadIdx.x;   // 256
    const float* row = logits + (size_t)t*Vv;
    __shared__ float rm[256], rs[256];
    float m = -1e30f, s = 0.f;
    for (int v = tid; v < Vv; v += 256){
        float x = row[v];
        float nm = fmaxf(m, x);
        s = s*expf(m - nm) + expf(x - nm);
        m = nm;
    }
    rm[tid] = m; rs[tid] = s; __syncthreads();
    for (int o = 128; o > 0; o >>= 1){
        if (tid < o){
            float m2 = rm[tid+o], s2 = rs[tid+o];
            float nm = fmaxf(rm[tid], m2);
            rs[tid] = rs[tid]*expf(rm[tid]-nm) + s2*expf(m2-nm);
            rm[tid] = nm;
        }
        __syncthreads();
    }
    if (tid == 0){
        float lse = logf(rs[0]) + rm[0];
        int lbl = labels[t];
        g_nll[t] = (lbl != -100) ? (lse - row[lbl < 0 ? 0 : lbl]) : 0.0f;
    }
}

__global__ void k_final(const int* __restrict__ labels, float* lossp){
    int tid = threadIdx.x;               // 64
    __shared__ int   ccnt[64];
    __shared__ float contrib[64];
    ccnt[tid] = 0; __syncthreads();
    for (int i = tid; i < Ll*Tt*KK; i += 64) atomicAdd(&ccnt[g_sel[i]], 1);
    float sp = 0.f;
    for (int r = 0; r < Ll*Tt; r++) sp += g_probs[(size_t)r*Ee + tid];
    __syncthreads();
    contrib[tid] = sp * (float)ccnt[tid];
    __syncthreads();
    if (tid == 0){
        float aux = 0.f;
        for (int e = 0; e < Ee; e++) aux += contrib[e];
        float NN = (float)(Ll*Tt);
        aux = aux / (NN*NN) * (float)Ee;
        float ce = 0.f; int valid = 0;
        for (int t = 0; t < Tt; t++){ ce += g_nll[t]; if (labels[t] != -100) valid++; }
        ce /= (valid > 0 ? (float)valid : 1.0f);
        if (lossp) *lossp = ce + 0.01f*aux;
    }
}

// ------------------------------------------------------------------
extern "C" void kernel_launch(void* const* d_in, const int* in_sizes, int n_in,
                              void* d_out, int out_size){
    const int*   ids    = (const int*)  d_in[0];
    const int*   labels = (const int*)  d_in[1];
    const float* embed  = (const float*)d_in[2];
    const float* ln1    = (const float*)d_in[3];
    const float* Wq     = (const float*)d_in[4];
    const float* Wk     = (const float*)d_in[5];
    const float* Wv     = (const float*)d_in[6];
    const float* Wo     = (const float*)d_in[7];
    const float* ln2    = (const float*)d_in[8];
    const float* rw     = (const float*)d_in[9];
    const float* Wg     = (const float*)d_in[10];
    const float* Wu     = (const float*)d_in[11];
    const float* Wd     = (const float*)d_in[12];
    const float* fnw    = (const float*)d_in[13];

    float *fbp;
    cudaGetSymbolAddress((void**)&fbp, g_logits_fb);

    float* out = (float*)d_out;
    const size_t TV = (size_t)Tt * Vv;
    float* logits = ((size_t)out_size >= TV) ? out : fbp;
    float* lossp = nullptr;
    if ((size_t)out_size == TV + 1) lossp = out + TV;
    else if (out_size == 1)         lossp = out;

    k_embed<<<Tt, 256>>>(ids, embed);
    k_rmsnorm<<<Tt, 256>>>(ln1);

    for (int i = 0; i < Ll; i++){
        k_qkv<<<dim3(20, Tt/128), 256>>>(Wq + (size_t)i*Hh*NHh*HDd,
                                         Wk + (size_t)i*Hh*NKVv*HDd,
                                         Wv + (size_t)i*Hh*NKVv*HDd);
        k_rope2<<<Tt, 512>>>();
        k_scores<<<dim3(Tt/64, Tt/128, NHh), 256>>>();
        k_softmax<<<dim3(Tt, NHh), 128>>>();
        k_pv<<<dim3(1, Tt/128, NHh), 256>>>();
        k_wo<<<dim3(Hh/64, Tt/128), 256>>>(Wo + (size_t)i*NHh*HDd*Hh);
        k_norm_router<<<Tt, 256>>>(ln2 + (size_t)i*Hh, rw + (size_t)i*Hh*Ee, i);
        k_countscatter<<<1, 512>>>(i);
        k_moe_up<<<dim3(3, 96, 2), 256>>>(Wg, Wu);
        k_act<<<1536, 256>>>();
        k_moe_down<<<dim3(12, 96), 256>>>(Wd);
        const float* wnext = (i < Ll-1) ? (ln1 + (size_t)(i+1)*Hh) : fnw;
        k_combine_norm<<<Tt, 256>>>(wnext);
    }

    k_lmhead<<<dim3(Vv/64, Tt/128), 256>>>(embed, logits);
    k_ce<<<Tt, 256>>>(logits, labels);
    k_final<<<1, 64>>>(labels, lossp);
}

// round 8
// speedup vs baseline: 1.4076x; 1.0011x over previous
#include <cuda_runtime.h>
#include <cuda_bf16.h>
#include <math.h>

// ---- model dims ----
#define Tt   512
#define Hh   768
#define Ll   4
#define NHh  12
#define NKVv 4
#define HDd  64
#define Ee   64
#define Ff   192
#define KK   8
#define Vv   32000
#define REP  3   // NH / NKV
#define MAXTILES 128

// ---- fp32 scratch ----
__device__ float g_x[Tt*Hh];
__device__ float g_q[Tt*NHh*HDd];
__device__ float g_k[Tt*NKVv*HDd];
__device__ float g_v[Tt*NKVv*HDd];
__device__ float g_scores[(size_t)NHh*Tt*Tt];
__device__ float g_probs[Ll*Tt*Ee];
__device__ int   g_sel[Ll*Tt*KK];
__device__ float g_topw[Tt*KK];
__device__ int   g_cnt[Ee];
__device__ int   g_off[Ee+1];
__device__ int   g_pairs[Tt*KK];
__device__ int   g_ntiles;
__device__ int   g_tile_e[MAXTILES];
__device__ int   g_tile_base[MAXTILES];
__device__ int   g_tile_rows[MAXTILES];
__device__ float g_actg[Tt*KK*Ff];
__device__ float g_actu[Tt*KK*Ff];
__device__ float g_slotout[Tt*KK*Hh];
__device__ float g_nll[Tt];
__device__ float g_logits_fb[(size_t)Tt*Vv];

// ---- packed bf16 hi/lo word arrays for ACTIVATIONS only ----
__device__ __align__(16) unsigned g_xnh[Tt*384],  g_xnl[Tt*384];
__device__ __align__(16) unsigned g_qh[Tt*384],   g_ql[Tt*384];
__device__ __align__(16) unsigned g_kh[Tt*128],   g_kl[Tt*128];
__device__ __align__(16) unsigned g_sph[(size_t)NHh*Tt*256], g_spl[(size_t)NHh*Tt*256];
__device__ __align__(16) unsigned g_ath[Tt*384],  g_atl[Tt*384];
__device__ __align__(16) unsigned g_acth[Tt*KK*96], g_actl[Tt*KK*96];

// ------------------------------------------------------------------
__device__ __forceinline__ unsigned prmt_hi(unsigned a, unsigned b){
    unsigned d; asm("prmt.b32 %0,%1,%2,0x7632;" : "=r"(d) : "r"(a), "r"(b)); return d;
}
__device__ __forceinline__ unsigned pack_bf16x2(float lo, float hi){
    unsigned d; asm("cvt.rn.bf16x2.f32 %0,%1,%2;" : "=r"(d) : "f"(hi), "f"(lo)); return d;
}
__device__ __forceinline__ void split_pair(float x0, float x1, unsigned &hi, unsigned &lo){
    unsigned u0 = __float_as_uint(x0), u1 = __float_as_uint(x1);
    hi = prmt_hi(u0, u1);
    float r0 = x0 - __uint_as_float(u0 & 0xffff0000u);
    float r1 = x1 - __uint_as_float(u1 & 0xffff0000u);
    lo = pack_bf16x2(r0, r1);
}

#define MMA_BF16(d, a, b) \
    asm volatile("mma.sync.aligned.m16n8k16.row.col.f32.bf16.bf16.f32 " \
                 "{%0,%1,%2,%3},{%4,%5,%6,%7},{%8,%9},{%0,%1,%2,%3};" \
                 : "+f"(d[0]),"+f"(d[1]),"+f"(d[2]),"+f"(d[3]) \
                 : "r"(a[0]),"r"(a[1]),"r"(a[2]),"r"(a[3]),"r"(b[0]),"r"(b[1]))

// cp.async helpers (16B)
__device__ __forceinline__ void cp16(void* s, const void* g){
    unsigned sa = (unsigned)__cvta_generic_to_shared(s);
    asm volatile("cp.async.cg.shared.global [%0], [%1], 16;\n" :: "r"(sa), "l"(g));
}
#define CP_COMMIT() asm volatile("cp.async.commit_group;\n" ::: "memory")
#define CP_WAIT(n)  asm volatile("cp.async.wait_group %0;\n" :: "n"(n) : "memory")

// ------------------------------------------------------------------
// cp.async double-buffered GEMM core. Block 128x64, 8 warps (4Mx2N), warp 32x32.
// k-step = 16 K (8 packed words). A: packed hi/lo words [rows, Kw], rows via
// rowidx[] or arow0+r. B: BMODE 0 = packed [N,Kw]; 1 = fp32 [N,K] rm;
// 2 = fp32 [K,N] rm. col0 = N-offset of this block's 64-wide tile.
template<int BMODE>
__device__ __forceinline__ void mm_async(
    const unsigned* __restrict__ Ah, const unsigned* __restrict__ Al,
    int ldaw, int arow0, const int* __restrict__ rowidx,
    const unsigned* __restrict__ Bph, const unsigned* __restrict__ Bpl, int ldbw,
    const float* __restrict__ Bf, int ldb,
    int col0, int Kw, float acc[2][4][4])
{
    __shared__ __align__(16) unsigned As_h[2][128][12];
    __shared__ __align__(16) unsigned As_l[2][128][12];
    __shared__ __align__(16) unsigned Bs[2][1536];

    int tid  = threadIdx.x;
    int lane = tid & 31, warp = tid >> 5;
    int wm = warp & 3, wn = warp >> 2;
    int gq = lane >> 2, tg = lane & 3;

    // A stage assignment: 128 rows x 2 chunks (of 4 words) per array
    int ar = tid >> 1, ac = (tid & 1)*4;
    int gr = rowidx ? rowidx[ar] : (arow0 + ar);
    const unsigned* gAh = Ah + (size_t)gr*ldaw + ac;
    const unsigned* gAl = Al + (size_t)gr*ldaw + ac;

    auto stage = [&](int ks, int buf){
        cp16(&As_h[buf][ar][ac], gAh + ks*8);
        cp16(&As_l[buf][ar][ac], gAl + ks*8);
        if (BMODE == 0){
            int a = tid >> 7, rem = tid & 127;
            int row = rem >> 1, ch = (rem & 1)*4;
            const unsigned* src = (a ? Bpl : Bph) + (size_t)(col0+row)*ldbw + ks*8 + ch;
            cp16(&Bs[buf][a*768 + row*12 + ch], src);
        } else if (BMODE == 1){
            int row = tid >> 2, ch = (tid & 3)*4;
            const float* src = Bf + (size_t)(col0+row)*ldb + ks*16 + ch;
            cp16(&Bs[buf][row*20 + ch], src);
        } else {
            int row = tid >> 4, ch = (tid & 15)*4;
            const float* src = Bf + (size_t)(ks*16 + row)*ldb + col0 + ch;
            cp16(&Bs[buf][row*68 + ch], src);
        }
    };

    int nst = Kw >> 3;
    stage(0, 0); CP_COMMIT();

    for (int ks = 0; ks < nst; ks++){
        int buf = ks & 1;
        if (ks + 1 < nst){ stage(ks+1, buf^1); CP_COMMIT(); CP_WAIT(1); }
        else             { CP_WAIT(0); }
        __syncthreads();

        unsigned ah[2][4], al[2][4], bh[4][2], bl[4][2];
        #pragma unroll
        for (int mt = 0; mt < 2; mt++){
            int rb = wm*32 + mt*16 + gq;
            ah[mt][0] = As_h[buf][rb][tg];     ah[mt][1] = As_h[buf][rb+8][tg];
            ah[mt][2] = As_h[buf][rb][tg+4];   ah[mt][3] = As_h[buf][rb+8][tg+4];
            al[mt][0] = As_l[buf][rb][tg];     al[mt][1] = As_l[buf][rb+8][tg];
            al[mt][2] = As_l[buf][rb][tg+4];   al[mt][3] = As_l[buf][rb+8][tg+4];
        }
        #pragma unroll
        for (int nt = 0; nt < 4; nt++){
            int nb = wn*32 + nt*8 + gq;
            if (BMODE == 0){
                bh[nt][0] = Bs[buf][nb*12 + tg];       bh[nt][1] = Bs[buf][nb*12 + tg+4];
                bl[nt][0] = Bs[buf][768 + nb*12 + tg]; bl[nt][1] = Bs[buf][768 + nb*12 + tg+4];
            } else if (BMODE == 1){
                const float* bp = (const float*)Bs[buf];
                float2 v0 = *(const float2*)&bp[nb*20 + 2*tg];
                float2 v1 = *(const float2*)&bp[nb*20 + 2*tg + 8];
                split_pair(v0.x, v0.y, bh[nt][0], bl[nt][0]);
                split_pair(v1.x, v1.y, bh[nt][1], bl[nt][1]);
            } else {
                const float* bp = (const float*)Bs[buf];
                split_pair(bp[(2*tg  )*68 + nb], bp[(2*tg+1)*68 + nb], bh[nt][0], bl[nt][0]);
                split_pair(bp[(2*tg+8)*68 + nb], bp[(2*tg+9)*68 + nb], bh[nt][1], bl[nt][1]);
            }
        }
        #pragma unroll
        for (int mt = 0; mt < 2; mt++)
            #pragma unroll
            for (int nt = 0; nt < 4; nt++){
                MMA_BF16(acc[mt][nt], ah[mt], bh[nt]);
                MMA_BF16(acc[mt][nt], al[mt], bh[nt]);
                MMA_BF16(acc[mt][nt], ah[mt], bl[nt]);
            }
        __syncthreads();
    }
}

#define MM_PROLOGUE() \
    float acc[2][4][4]; \
    _Pragma("unroll") \
    for (int i = 0; i < 2; i++) \
        _Pragma("unroll") \
        for (int j = 0; j < 4; j++) \
            _Pragma("unroll") \
            for (int l = 0; l < 4; l++) acc[i][j][l] = 0.f;

__device__ __forceinline__ void epi_f32(float* C, int ldc, int row0, int col0,
                                        int doacc, float acc[2][4][4]){
    int tid = threadIdx.x, lane = tid & 31, warp = tid >> 5;
    int wm = warp & 3, wn = warp >> 2;
    int gq = lane >> 2, tg = lane & 3;
    #pragma unroll
    for (int mt = 0; mt < 2; mt++){
        int r0 = row0 + wm*32 + mt*16 + gq;
        #pragma unroll
        for (int nt = 0; nt < 4; nt++){
            int c0 = col0 + wn*32 + nt*8 + tg*2;
            float* p0 = &C[(size_t)r0*ldc + c0];
            float* p1 = &C[(size_t)(r0+8)*ldc + c0];
            if (doacc){
                p0[0] += acc[mt][nt][0]; p0[1] += acc[mt][nt][1];
                p1[0] += acc[mt][nt][2]; p1[1] += acc[mt][nt][3];
            } else {
                p0[0] = acc[mt][nt][0]; p0[1] = acc[mt][nt][1];
                p1[0] = acc[mt][nt][2]; p1[1] = acc[mt][nt][3];
            }
        }
    }
}

// ---- GEMM kernels ----
__global__ __launch_bounds__(256, 2)
void k_qkv(const float* __restrict__ Wq, const float* __restrict__ Wk,
           const float* __restrict__ Wv){
    MM_PROLOGUE();
    int bx = blockIdx.x, row0 = blockIdx.y*128;
    if (bx < 12){
        mm_async<2>(g_xnh, g_xnl, 384, row0, nullptr, nullptr, nullptr, 0,
                    Wq, 768, bx*64, 384, acc);
        epi_f32(g_q, 768, row0, bx*64, 0, acc);
    } else if (bx < 16){
        mm_async<2>(g_xnh, g_xnl, 384, row0, nullptr, nullptr, nullptr, 0,
                    Wk, 256, (bx-12)*64, 384, acc);
        epi_f32(g_k, 256, row0, (bx-12)*64, 0, acc);
    } else {
        mm_async<2>(g_xnh, g_xnl, 384, row0, nullptr, nullptr, nullptr, 0,
                    Wv, 256, (bx-16)*64, 384, acc);
        epi_f32(g_v, 256, row0, (bx-16)*64, 0, acc);
    }
}

__global__ __launch_bounds__(256, 2)
void k_scores(){
    int h = blockIdx.z;
    if ((int)blockIdx.x >= 2*(int)blockIdx.y + 2) return;
    MM_PROLOGUE();
    int row0 = blockIdx.y*128, col0 = blockIdx.x*64;
    mm_async<0>(g_qh + h*32, g_ql + h*32, 384, row0, nullptr,
                g_kh + (h/REP)*32, g_kl + (h/REP)*32, 128,
                nullptr, 0, col0, 32, acc);
    epi_f32(g_scores + (size_t)h*Tt*Tt, Tt, row0, col0, 0, acc);
}

__global__ __launch_bounds__(256, 2)
void k_pv(){
    int h = blockIdx.z;
    MM_PROLOGUE();
    int row0 = blockIdx.y*128;
    mm_async<2>(g_sph + (size_t)h*Tt*256, g_spl + (size_t)h*Tt*256, 256, row0, nullptr,
                nullptr, nullptr, 0,
                g_v, 256, (h/REP)*64, 256, acc);
    int tid = threadIdx.x, lane = tid & 31, warp = tid >> 5;
    int wm = warp & 3, wn = warp >> 2;
    int gq = lane >> 2, tg = lane & 3;
    #pragma unroll
    for (int mt = 0; mt < 2; mt++){
        int r0 = row0 + wm*32 + mt*16 + gq;
        #pragma unroll
        for (int nt = 0; nt < 4; nt++){
            int wrd = h*32 + wn*16 + nt*4 + tg;
            unsigned hi, lo;
            split_pair(acc[mt][nt][0], acc[mt][nt][1], hi, lo);
            g_ath[(size_t)r0*384 + wrd] = hi; g_atl[(size_t)r0*384 + wrd] = lo;
            split_pair(acc[mt][nt][2], acc[mt][nt][3], hi, lo);
            g_ath[(size_t)(r0+8)*384 + wrd] = hi; g_atl[(size_t)(r0+8)*384 + wrd] = lo;
        }
    }
}

__global__ __launch_bounds__(256, 2)
void k_wo(const float* __restrict__ Wo){
    MM_PROLOGUE();
    int row0 = blockIdx.y*128, col0 = blockIdx.x*64;
    mm_async<2>(g_ath, g_atl, 384, row0, nullptr, nullptr, nullptr, 0,
                Wo, 768, col0, 384, acc);
    epi_f32(g_x, 768, row0, col0, 1, acc);
}

__global__ __launch_bounds__(256, 2)
void k_lmhead(const float* __restrict__ embed, float* __restrict__ logits){
    MM_PROLOGUE();
    int row0 = blockIdx.y*128, col0 = blockIdx.x*64;
    mm_async<1>(g_xnh, g_xnl, 384, row0, nullptr, nullptr, nullptr, 0,
                embed, 768, col0, 384, acc);
    epi_f32(logits, Vv, row0, col0, 0, acc);
}

__global__ __launch_bounds__(256, 2)
void k_moe_up(const float* __restrict__ Wg, const float* __restrict__ Wu){
    int ti = blockIdx.y;
    if (ti >= g_ntiles) return;
    MM_PROLOGUE();
    __shared__ int rowidx[128];
    int e = g_tile_e[ti], base = g_tile_base[ti], rows = g_tile_rows[ti];
    int tid = threadIdx.x;
    if (tid < 128){
        int s = base + (tid < rows ? tid : rows-1);
        rowidx[tid] = g_pairs[s] >> 3;
    }
    __syncthreads();
    int colb = blockIdx.x*64;
    const float* W = (blockIdx.z ? Wu : Wg) + (size_t)e*Hh*Ff;
    mm_async<2>(g_xnh, g_xnl, 384, 0, rowidx, nullptr, nullptr, 0,
                W, Ff, colb, 384, acc);
    float* out = blockIdx.z ? g_actu : g_actg;
    int lane = tid & 31, warp = tid >> 5;
    int wm = warp & 3, wn = warp >> 2;
    int gq = lane >> 2, tg = lane & 3;
    #pragma unroll
    for (int mt = 0; mt < 2; mt++){
        #pragma unroll
        for (int hf = 0; hf < 2; hf++){
            int r = wm*32 + mt*16 + gq + hf*8;
            if (r < rows){
                float* op = &out[(size_t)(base + r)*Ff + colb + wn*32 + tg*2];
                #pragma unroll
                for (int nt = 0; nt < 4; nt++){
                    op[nt*8    ] = acc[mt][nt][hf*2];
                    op[nt*8 + 1] = acc[mt][nt][hf*2 + 1];
                }
            }
        }
    }
}

__global__ void k_act(){
    int i = blockIdx.x*256 + threadIdx.x;   // words
    if (i >= Tt*KK*96) return;
    float g0 = g_actg[2*i], g1 = g_actg[2*i + 1];
    float u0 = g_actu[2*i], u1 = g_actu[2*i + 1];
    float a0 = g0/(1.f+expf(-g0))*u0;
    float a1 = g1/(1.f+expf(-g1))*u1;
    unsigned hi, lo; split_pair(a0, a1, hi, lo);
    g_acth[i] = hi; g_actl[i] = lo;
}

__global__ __launch_bounds__(256, 2)
void k_moe_down(const float* __restrict__ Wd){
    int ti = blockIdx.y;
    if (ti >= g_ntiles) return;
    MM_PROLOGUE();
    __shared__ int rowidx[128];
    int e = g_tile_e[ti], base = g_tile_base[ti], rows = g_tile_rows[ti];
    int tid = threadIdx.x;
    if (tid < 128)
        rowidx[tid] = base + (tid < rows ? tid : rows-1);
    __syncthreads();
    int colb = blockIdx.x*64;
    mm_async<2>(g_acth, g_actl, 96, 0, rowidx, nullptr, nullptr, 0,
                Wd + (size_t)e*Ff*Hh, 768, colb, 96, acc);
    int lane = tid & 31, warp = tid >> 5;
    int wm = warp & 3, wn = warp >> 2;
    int gq = lane >> 2, tg = lane & 3;
    #pragma unroll
    for (int mt = 0; mt < 2; mt++){
        #pragma unroll
        for (int hf = 0; hf < 2; hf++){
            int r = wm*32 + mt*16 + gq + hf*8;
            if (r < rows){
                int pr = g_pairs[base + r];
                float w = g_topw[pr];
                float* op = &g_slotout[(size_t)pr*Hh + colb + wn*32 + tg*2];
                #pragma unroll
                for (int nt = 0; nt < 4; nt++){
                    op[nt*8    ] = w*acc[mt][nt][hf*2];
                    op[nt*8 + 1] = w*acc[mt][nt][hf*2 + 1];
                }
            }
        }
    }
}

// ------------------------------------------------------------------
__global__ void k_embed(const int* __restrict__ ids, const float* __restrict__ emb){
    int t = blockIdx.x;
    int id = ids[t];
    for (int h = threadIdx.x; h < Hh; h += blockDim.x)
        g_x[t*Hh + h] = emb[(size_t)id*Hh + h];
}

__global__ void k_rmsnorm(const float* __restrict__ w){
    int t = blockIdx.x; int tid = threadIdx.x;   // 256
    __shared__ float xs[Hh];
    __shared__ float red[256];
    float s = 0.f;
    #pragma unroll
    for (int c = 0; c < 3; c++){
        float v = g_x[t*Hh + tid + 256*c];
        xs[tid + 256*c] = v; s += v*v;
    }
    red[tid] = s; __syncthreads();
    for (int o = 128; o > 0; o >>= 1){ if (tid < o) red[tid] += red[tid+o]; __syncthreads(); }
    float r = rsqrtf(red[0] / (float)Hh + 1e-6f);
    __syncthreads();
    #pragma unroll
    for (int c = 0; c < 3; c++){
        int h = tid + 256*c;
        xs[h] = xs[h] * r * w[h];
    }
    __syncthreads();
    for (int wd = tid; wd < 384; wd += 256){
        unsigned hi, lo; split_pair(xs[2*wd], xs[2*wd+1], hi, lo);
        g_xnh[t*384 + wd] = hi; g_xnl[t*384 + wd] = lo;
    }
}

__global__ void k_rope2(){
    int t = blockIdx.x;
    int w = threadIdx.x >> 5, j = threadIdx.x & 31;
    const float* p = (w < 12) ? &g_q[t*Hh + w*HDd] : &g_k[t*(NKVv*HDd) + (w-12)*HDd];
    float inv = exp2f(-(float)(2*j) * (13.287712379549449f / 64.0f));
    float ang = (float)t * inv;
    float c = cosf(ang), s = sinf(ang);
    float x0 = p[j], x1 = p[j+32];
    float y0 = x0*c - x1*s;
    float y1 = x1*c + x0*s;
    unsigned full = 0xffffffffu;
    int m = j & 15;
    float sa = __shfl_sync(full, y0, 2*m);
    float sb = __shfl_sync(full, y0, 2*m + 1);
    float ta = __shfl_sync(full, y1, 2*m);
    float tb = __shfl_sync(full, y1, 2*m + 1);
    float f0 = (j < 16) ? sa : ta;
    float f1 = (j < 16) ? sb : tb;
    unsigned hi, lo; split_pair(f0, f1, hi, lo);
    if (w < 12){
        g_qh[t*384 + w*32 + j] = hi; g_ql[t*384 + w*32 + j] = lo;
    } else {
        g_kh[t*128 + (w-12)*32 + j] = hi; g_kl[t*128 + (w-12)*32 + j] = lo;
    }
}

__global__ void k_softmax(){
    int t = blockIdx.x, h = blockIdx.y, tid = threadIdx.x;   // 128 thr
    const float* row = g_scores + (size_t)h*Tt*Tt + (size_t)t*Tt;
    __shared__ float p[Tt];
    __shared__ float red[128];
    float m = -1e30f;
    for (int kk = tid; kk <= t; kk += 128){
        float v = row[kk]*0.125f;
        p[kk] = v; m = fmaxf(m, v);
    }
    red[tid] = m; __syncthreads();
    for (int o = 64; o > 0; o >>= 1){ if (tid < o) red[tid] = fmaxf(red[tid], red[tid+o]); __syncthreads(); }
    m = red[0]; __syncthreads();
    float s = 0.f;
    for (int kk = tid; kk <= t; kk += 128){
        float e = expf(p[kk] - m);
        p[kk] = e; s += e;
    }
    red[tid] = s; __syncthreads();
    for (int o = 64; o > 0; o >>= 1){ if (tid < o) red[tid] += red[tid+o]; __syncthreads(); }
    float inv = 1.0f / red[0];
    size_t obase = ((size_t)h*Tt + t)*256;
    for (int wd = tid; wd < 256; wd += 128){
        float f0 = (2*wd     <= t) ? p[2*wd]*inv     : 0.f;
        float f1 = (2*wd + 1 <= t) ? p[2*wd+1]*inv   : 0.f;
        unsigned hi, lo; split_pair(f0, f1, hi, lo);
        g_sph[obase + wd] = hi; g_spl[obase + wd] = lo;
    }
}

__global__ void k_norm_router(const float* __restrict__ w, const float* __restrict__ rw,
                              int layer){
    int t = blockIdx.x, tid = threadIdx.x;   // 256
    __shared__ float xs[Hh];
    __shared__ float red[256];
    __shared__ float lg[64];
    float loc[3]; float ss = 0.f;
    #pragma unroll
    for (int c = 0; c < 3; c++){
        float v = g_x[t*Hh + tid + 256*c];
        loc[c] = v; ss += v*v;
    }
    red[tid] = ss; __syncthreads();
    for (int o = 128; o > 0; o >>= 1){ if (tid < o) red[tid] += red[tid+o]; __syncthreads(); }
    float r = rsqrtf(red[0] / (float)Hh + 1e-6f);
    #pragma unroll
    for (int c = 0; c < 3; c++){
        int h = tid + 256*c;
        xs[h] = loc[c] * r * w[h];
    }
    __syncthreads();
    for (int wd = tid; wd < 384; wd += 256){
        unsigned hi, lo; split_pair(xs[2*wd], xs[2*wd+1], hi, lo);
        g_xnh[t*384 + wd] = hi; g_xnl[t*384 + wd] = lo;
    }
    if (tid < 64){
        float a0=0.f, a1=0.f, a2=0.f, a3=0.f;
        #pragma unroll 4
        for (int h = 0; h < Hh; h += 4){
            a0 += xs[h  ] * rw[(h  )*Ee + tid];
            a1 += xs[h+1] * rw[(h+1)*Ee + tid];
            a2 += xs[h+2] * rw[(h+2)*Ee + tid];
            a3 += xs[h+3] * rw[(h+3)*Ee + tid];
        }
        lg[tid] = (a0+a1) + (a2+a3);
    }
    __syncthreads();
    if (tid < 32){
        float v0 = lg[tid], v1 = lg[tid+32];
        float m = fmaxf(v0, v1);
        #pragma unroll
        for (int o = 16; o > 0; o >>= 1) m = fmaxf(m, __shfl_xor_sync(0xffffffffu, m, o));
        float e0 = expf(v0 - m), e1 = expf(v1 - m);
        float s = e0 + e1;
        #pragma unroll
        for (int o = 16; o > 0; o >>= 1) s += __shfl_xor_sync(0xffffffffu, s, o);
        float p0 = e0 / s, p1 = e1 / s;
        g_probs[((size_t)layer*Tt + t)*Ee + tid]      = p0;
        g_probs[((size_t)layer*Tt + t)*Ee + tid + 32] = p1;
        lg[tid] = p0; lg[tid+32] = p1;
        __syncwarp();
        float tv[KK]; int ti[KK]; float ws = 0.f;
        #pragma unroll
        for (int k = 0; k < KK; k++){
            float c0 = lg[tid], c1 = lg[tid+32];
            float bv; int bi;
            if (c0 >= c1){ bv = c0; bi = tid; } else { bv = c1; bi = tid+32; }
            #pragma unroll
            for (int o = 16; o > 0; o >>= 1){
                float ov = __shfl_xor_sync(0xffffffffu, bv, o);
                int   oi = __shfl_xor_sync(0xffffffffu, bi, o);
                if (ov > bv || (ov == bv && oi < bi)){ bv = ov; bi = oi; }
            }
            tv[k] = bv; ti[k] = bi; ws += bv;
            if (tid == 0) lg[bi] = -1.0f;
            __syncwarp();
        }
        if (tid == 0){
            float inv = 1.0f / ws;
            #pragma unroll
            for (int k = 0; k < KK; k++){
                g_sel[((size_t)layer*Tt + t)*KK + k] = ti[k];
                g_topw[t*KK + k] = tv[k] * inv;
            }
        }
    }
}

__global__ void k_countscatter(int layer){
    __shared__ int c[Ee], off[Ee+1], fill[Ee];
    int tid = threadIdx.x;   // 512
    if (tid < Ee) c[tid] = 0;
    __syncthreads();
    const int* sel = &g_sel[(size_t)layer*Tt*KK];
    for (int i = tid; i < Tt*KK; i += 512) atomicAdd(&c[sel[i]], 1);
    __syncthreads();
    if (tid == 0){
        int run = 0;
        for (int e = 0; e < Ee; e++){ off[e] = run; run += c[e]; }
        off[Ee] = run;
        int n = 0;
        for (int e = 0; e < Ee; e++){
            for (int b = 0; b < c[e]; b += 128){
                g_tile_e[n] = e;
                g_tile_base[n] = off[e] + b;
                g_tile_rows[n] = min(128, c[e] - b);
                n++;
            }
        }
        g_ntiles = n;
    }
    __syncthreads();
    if (tid < Ee){ g_cnt[tid] = c[tid]; g_off[tid] = off[tid]; fill[tid] = off[tid]; }
    if (tid == 0) g_off[Ee] = off[Ee];
    __syncthreads();
    for (int i = tid; i < Tt*KK; i += 512){
        int e = sel[i];
        int pos = atomicAdd(&fill[e], 1);
        g_pairs[pos] = i;
    }
}

__global__ void k_combine_norm(const float* __restrict__ w){
    int t = blockIdx.x, tid = threadIdx.x;   // 256
    __shared__ float xs[Hh];
    __shared__ float red[256];
    float ss = 0.f;
    #pragma unroll
    for (int c = 0; c < 3; c++){
        int h = tid + 256*c;
        float s = g_x[t*Hh + h];
        #pragma unroll
        for (int sl = 0; sl < KK; sl++)
            s += g_slotout[(size_t)(t*KK + sl)*Hh + h];
        g_x[t*Hh + h] = s;
        xs[h] = s; ss += s*s;
    }
    red[tid] = ss; __syncthreads();
    for (int o = 128; o > 0; o >>= 1){ if (tid < o) red[tid] += red[tid+o]; __syncthreads(); }
    float r = rsqrtf(red[0] / (float)Hh + 1e-6f);
    __syncthreads();
    #pragma unroll
    for (int c = 0; c < 3; c++){
        int h = tid + 256*c;
        xs[h] = xs[h] * r * w[h];
    }
    __syncthreads();
    for (int wd = tid; wd < 384; wd += 256){
        unsigned hi, lo; split_pair(xs[2*wd], xs[2*wd+1], hi, lo);
        g_xnh[t*384 + wd] = hi; g_xnl[t*384 + wd] = lo;
    }
}

__global__ void k_ce(const float* __restrict__ logits, const int* __restrict__ labels){
    int t = blockIdx.x, tid = threadIdx.x;   // 256
    const float* row = logits + (size_t)t*Vv;
    __shared__ float rm[256], rs[256];
    float m = -1e30f, s = 0.f;
    for (int v = tid; v < Vv; v += 256){
        float x = row[v];
        float nm = fmaxf(m, x);
        s = s*expf(m - nm) + expf(x - nm);
        m = nm;
    }
    rm[tid] = m; rs[tid] = s; __syncthreads();
    for (int o = 128; o > 0; o >>= 1){
        if (tid < o){
            float m2 = rm[tid+o], s2 = rs[tid+o];
            float nm = fmaxf(rm[tid], m2);
            rs[tid] = rs[tid]*expf(rm[tid]-nm) + s2*expf(m2-nm);
            rm[tid] = nm;
        }
        __syncthreads();
    }
    if (tid == 0){
        float lse = logf(rs[0]) + rm[0];
        int lbl = labels[t];
        g_nll[t] = (lbl != -100) ? (lse - row[lbl < 0 ? 0 : lbl]) : 0.0f;
    }
}

__global__ void k_final(const int* __restrict__ labels, float* lossp){
    int tid = threadIdx.x;               // 64
    __shared__ int   ccnt[64];
    __shared__ float contrib[64];
    ccnt[tid] = 0; __syncthreads();
    for (int i = tid; i < Ll*Tt*KK; i += 64) atomicAdd(&ccnt[g_sel[i]], 1);
    float sp = 0.f;
    for (int r = 0; r < Ll*Tt; r++) sp += g_probs[(size_t)r*Ee + tid];
    __syncthreads();
    contrib[tid] = sp * (float)ccnt[tid];
    __syncthreads();
    if (tid == 0){
        float aux = 0.f;
        for (int e = 0; e < Ee; e++) aux += contrib[e];
        float NN = (float)(Ll*Tt);
        aux = aux / (NN*NN) * (float)Ee;
        float ce = 0.f; int valid = 0;
        for (int t = 0; t < Tt; t++){ ce += g_nll[t]; if (labels[t] != -100) valid++; }
        ce /= (valid > 0 ? (float)valid : 1.0f);
        if (lossp) *lossp = ce + 0.01f*aux;
    }
}

// ------------------------------------------------------------------
extern "C" void kernel_launch(void* const* d_in, const int* in_sizes, int n_in,
                              void* d_out, int out_size){
    const int*   ids    = (const int*)  d_in[0];
    const int*   labels = (const int*)  d_in[1];
    const float* embed  = (const float*)d_in[2];
    const float* ln1    = (const float*)d_in[3];
    const float* Wq     = (const float*)d_in[4];
    const float* Wk     = (const float*)d_in[5];
    const float* Wv     = (const float*)d_in[6];
    const float* Wo     = (const float*)d_in[7];
    const float* ln2    = (const float*)d_in[8];
    const float* rw     = (const float*)d_in[9];
    const float* Wg     = (const float*)d_in[10];
    const float* Wu     = (const float*)d_in[11];
    const float* Wd     = (const float*)d_in[12];
    const float* fnw    = (const float*)d_in[13];

    float *fbp;
    cudaGetSymbolAddress((void**)&fbp, g_logits_fb);

    float* out = (float*)d_out;
    const size_t TV = (size_t)Tt * Vv;
    float* logits = ((size_t)out_size >= TV) ? out : fbp;
    float* lossp = nullptr;
    if ((size_t)out_size == TV + 1) lossp = out + TV;
    else if (out_size == 1)         lossp = out;

    k_embed<<<Tt, 256>>>(ids, embed);
    k_rmsnorm<<<Tt, 256>>>(ln1);

    for (int i = 0; i < Ll; i++){
        k_qkv<<<dim3(20, Tt/128), 256>>>(Wq + (size_t)i*Hh*NHh*HDd,
                                         Wk + (size_t)i*Hh*NKVv*HDd,
                                         Wv + (size_t)i*Hh*NKVv*HDd);
        k_rope2<<<Tt, 512>>>();
        k_scores<<<dim3(Tt/64, Tt/128, NHh), 256>>>();
        k_softmax<<<dim3(Tt, NHh), 128>>>();
        k_pv<<<dim3(1, Tt/128, NHh), 256>>>();
        k_wo<<<dim3(Hh/64, Tt/128), 256>>>(Wo + (size_t)i*NHh*HDd*Hh);
        k_norm_router<<<Tt, 256>>>(ln2 + (size_t)i*Hh, rw + (size_t)i*Hh*Ee, i);
        k_countscatter<<<1, 512>>>(i);
        k_moe_up<<<dim3(3, 96, 2), 256>>>(Wg, Wu);
        k_act<<<1536, 256>>>();
        k_moe_down<<<dim3(12, 96), 256>>>(Wd);
        const float* wnext = (i < Ll-1) ? (ln1 + (size_t)(i+1)*Hh) : fnw;
        k_combine_norm<<<Tt, 256>>>(wnext);
    }

    k_lmhead<<<dim3(Vv/64, Tt/128), 256>>>(embed, logits);
    k_ce<<<Tt, 256>>>(logits, labels);
    k_final<<<1, 64>>>(labels, lossp);
}

// round 9
// speedup vs baseline: 1.6186x; 1.1499x over previous
#include <cuda_runtime.h>
#include <cuda_bf16.h>
#include <math.h>

// ---- model dims ----
#define Tt   512
#define Hh   768
#define Ll   4
#define NHh  12
#define NKVv 4
#define HDd  64
#define Ee   64
#define Ff   192
#define KK   8
#define Vv   32000
#define REP  3   // NH / NKV
#define MAXTILES 128

// ---- fp32 scratch ----
__device__ float g_x[Tt*Hh];
__device__ float g_q[Tt*NHh*HDd];
__device__ float g_k[Tt*NKVv*HDd];
__device__ float g_v[Tt*NKVv*HDd];
__device__ float g_scores[(size_t)NHh*Tt*Tt];
__device__ float g_probs[Ll*Tt*Ee];
__device__ int   g_sel[Ll*Tt*KK];
__device__ float g_topw[Tt*KK];
__device__ int   g_cnt[Ee];
__device__ int   g_off[Ee+1];
__device__ int   g_pairs[Tt*KK];
__device__ int   g_ntiles;
__device__ int   g_tile_e[MAXTILES];
__device__ int   g_tile_base[MAXTILES];
__device__ int   g_tile_rows[MAXTILES];
__device__ float g_actg[Tt*KK*Ff];
__device__ float g_actu[Tt*KK*Ff];
__device__ float g_slotout[Tt*KK*Hh];
__device__ float g_nll[Tt];
__device__ float g_logits_fb[(size_t)Tt*Vv];

// ---- packed bf16 hi/lo word arrays for ACTIVATIONS only ----
__device__ __align__(16) unsigned g_xnh[Tt*384],  g_xnl[Tt*384];
__device__ __align__(16) unsigned g_qh[Tt*384],   g_ql[Tt*384];
__device__ __align__(16) unsigned g_kh[Tt*128],   g_kl[Tt*128];
__device__ __align__(16) unsigned g_sph[(size_t)NHh*Tt*256], g_spl[(size_t)NHh*Tt*256];
__device__ __align__(16) unsigned g_ath[Tt*384],  g_atl[Tt*384];
__device__ __align__(16) unsigned g_acth[Tt*KK*96], g_actl[Tt*KK*96];

// ------------------------------------------------------------------
__device__ __forceinline__ unsigned prmt_hi(unsigned a, unsigned b){
    unsigned d; asm("prmt.b32 %0,%1,%2,0x7632;" : "=r"(d) : "r"(a), "r"(b)); return d;
}
__device__ __forceinline__ unsigned pack_bf16x2(float lo, float hi){
    unsigned d; asm("cvt.rn.bf16x2.f32 %0,%1,%2;" : "=r"(d) : "f"(hi), "f"(lo)); return d;
}
__device__ __forceinline__ void split_pair(float x0, float x1, unsigned &hi, unsigned &lo){
    unsigned u0 = __float_as_uint(x0), u1 = __float_as_uint(x1);
    hi = prmt_hi(u0, u1);
    float r0 = x0 - __uint_as_float(u0 & 0xffff0000u);
    float r1 = x1 - __uint_as_float(u1 & 0xffff0000u);
    lo = pack_bf16x2(r0, r1);
}

#define MMA_BF16(d, a, b) \
    asm volatile("mma.sync.aligned.m16n8k16.row.col.f32.bf16.bf16.f32 " \
                 "{%0,%1,%2,%3},{%4,%5,%6,%7},{%8,%9},{%0,%1,%2,%3};" \
                 : "+f"(d[0]),"+f"(d[1]),"+f"(d[2]),"+f"(d[3]) \
                 : "r"(a[0]),"r"(a[1]),"r"(a[2]),"r"(a[3]),"r"(b[0]),"r"(b[1]))

// cp.async helpers (16B)
__device__ __forceinline__ void cp16(void* s, const void* g){
    unsigned sa = (unsigned)__cvta_generic_to_shared(s);
    asm volatile("cp.async.cg.shared.global [%0], [%1], 16;\n" :: "r"(sa), "l"(g));
}
#define CP_COMMIT() asm volatile("cp.async.commit_group;\n" ::: "memory")
#define CP_WAIT(n)  asm volatile("cp.async.wait_group %0;\n" :: "n"(n) : "memory")

// ------------------------------------------------------------------
// cp.async double-buffered GEMM core. Block tile (NW*16) x 64, NW warps
// (NW/2 along M, 2 along N), warp tile 32x32, k-step = 16 K (8 packed words).
// A: packed hi/lo words [rows, ldaw], rows via rowidx[] or arow0+r.
// B: BMODE 0 = packed [N,Kw] (row base = col0); 1 = fp32 [N,K] rm;
//    2 = fp32 [K,N] rm.  col0 = N-offset (or packed row base for BMODE0).
template<int BMODE, int NW>
__device__ __forceinline__ void mm_async(
    const unsigned* __restrict__ Ah, const unsigned* __restrict__ Al,
    int ldaw, int arow0, const int* __restrict__ rowidx,
    const unsigned* __restrict__ Bph, const unsigned* __restrict__ Bpl, int ldbw,
    const float* __restrict__ Bf, int ldb,
    int col0, int Kw, float acc[2][4][4])
{
    constexpr int MR  = NW*16;
    constexpr int NTH = NW*32;
    __shared__ __align__(16) unsigned As_h[2][MR][12];
    __shared__ __align__(16) unsigned As_l[2][MR][12];
    __shared__ __align__(16) unsigned Bs[2][1536];

    int tid  = threadIdx.x;
    int lane = tid & 31, warp = tid >> 5;
    int wm = warp % (NW/2), wn = warp / (NW/2);
    int gq = lane >> 2, tg = lane & 3;

    int ar = tid >> 1, ac = (tid & 1)*4;
    int gr = rowidx ? rowidx[ar] : (arow0 + ar);
    const unsigned* gAh = Ah + (size_t)gr*ldaw + ac;
    const unsigned* gAl = Al + (size_t)gr*ldaw + ac;

    auto stage = [&](int ks, int buf){
        cp16(&As_h[buf][ar][ac], gAh + ks*8);
        cp16(&As_l[buf][ar][ac], gAl + ks*8);
        #pragma unroll
        for (int it = 0; it < 256/NTH; it++){
            int t2 = tid + it*NTH;
            if (BMODE == 0){
                int a = t2 >> 7, rem = t2 & 127;
                int row = rem >> 1, ch = (rem & 1)*4;
                const unsigned* src = (a ? Bpl : Bph) + (size_t)(col0+row)*ldbw + ks*8 + ch;
                cp16(&Bs[buf][a*768 + row*12 + ch], src);
            } else if (BMODE == 1){
                int row = t2 >> 2, ch = (t2 & 3)*4;
                const float* src = Bf + (size_t)(col0+row)*ldb + ks*16 + ch;
                cp16(&Bs[buf][row*20 + ch], src);
            } else {
                int row = t2 >> 4, ch = (t2 & 15)*4;
                const float* src = Bf + (size_t)(ks*16 + row)*ldb + col0 + ch;
                cp16(&Bs[buf][row*68 + ch], src);
            }
        }
    };

    int nst = Kw >> 3;
    stage(0, 0); CP_COMMIT();

    for (int ks = 0; ks < nst; ks++){
        int buf = ks & 1;
        if (ks + 1 < nst){ stage(ks+1, buf^1); CP_COMMIT(); CP_WAIT(1); }
        else             { CP_WAIT(0); }
        __syncthreads();

        unsigned ah[2][4], al[2][4], bh[4][2], bl[4][2];
        #pragma unroll
        for (int mt = 0; mt < 2; mt++){
            int rb = wm*32 + mt*16 + gq;
            ah[mt][0] = As_h[buf][rb][tg];     ah[mt][1] = As_h[buf][rb+8][tg];
            ah[mt][2] = As_h[buf][rb][tg+4];   ah[mt][3] = As_h[buf][rb+8][tg+4];
            al[mt][0] = As_l[buf][rb][tg];     al[mt][1] = As_l[buf][rb+8][tg];
            al[mt][2] = As_l[buf][rb][tg+4];   al[mt][3] = As_l[buf][rb+8][tg+4];
        }
        #pragma unroll
        for (int nt = 0; nt < 4; nt++){
            int nb = wn*32 + nt*8 + gq;
            if (BMODE == 0){
                bh[nt][0] = Bs[buf][nb*12 + tg];       bh[nt][1] = Bs[buf][nb*12 + tg+4];
                bl[nt][0] = Bs[buf][768 + nb*12 + tg]; bl[nt][1] = Bs[buf][768 + nb*12 + tg+4];
            } else if (BMODE == 1){
                const float* bp = (const float*)Bs[buf];
                float2 v0 = *(const float2*)&bp[nb*20 + 2*tg];
                float2 v1 = *(const float2*)&bp[nb*20 + 2*tg + 8];
                split_pair(v0.x, v0.y, bh[nt][0], bl[nt][0]);
                split_pair(v1.x, v1.y, bh[nt][1], bl[nt][1]);
            } else {
                const float* bp = (const float*)Bs[buf];
                split_pair(bp[(2*tg  )*68 + nb], bp[(2*tg+1)*68 + nb], bh[nt][0], bl[nt][0]);
                split_pair(bp[(2*tg+8)*68 + nb], bp[(2*tg+9)*68 + nb], bh[nt][1], bl[nt][1]);
            }
        }
        #pragma unroll
        for (int mt = 0; mt < 2; mt++)
            #pragma unroll
            for (int nt = 0; nt < 4; nt++){
                MMA_BF16(acc[mt][nt], ah[mt], bh[nt]);
                MMA_BF16(acc[mt][nt], al[mt], bh[nt]);
                MMA_BF16(acc[mt][nt], ah[mt], bl[nt]);
            }
        __syncthreads();
    }
}

#define MM_PROLOGUE() \
    float acc[2][4][4]; \
    _Pragma("unroll") \
    for (int i = 0; i < 2; i++) \
        _Pragma("unroll") \
        for (int j = 0; j < 4; j++) \
            _Pragma("unroll") \
            for (int l = 0; l < 4; l++) acc[i][j][l] = 0.f;

template<int NW>
__device__ __forceinline__ void epi_f32(float* C, int ldc, int row0, int col0,
                                        int doacc, float acc[2][4][4]){
    int tid = threadIdx.x, lane = tid & 31, warp = tid >> 5;
    int wm = warp % (NW/2), wn = warp / (NW/2);
    int gq = lane >> 2, tg = lane & 3;
    #pragma unroll
    for (int mt = 0; mt < 2; mt++){
        int r0 = row0 + wm*32 + mt*16 + gq;
        #pragma unroll
        for (int nt = 0; nt < 4; nt++){
            int c0 = col0 + wn*32 + nt*8 + tg*2;
            float* p0 = &C[(size_t)r0*ldc + c0];
            float* p1 = &C[(size_t)(r0+8)*ldc + c0];
            if (doacc){
                p0[0] += acc[mt][nt][0]; p0[1] += acc[mt][nt][1];
                p1[0] += acc[mt][nt][2]; p1[1] += acc[mt][nt][3];
            } else {
                p0[0] = acc[mt][nt][0]; p0[1] = acc[mt][nt][1];
                p1[0] = acc[mt][nt][2]; p1[1] = acc[mt][nt][3];
            }
        }
    }
}

// ---- GEMM kernels ----
__global__ __launch_bounds__(128, 4)
void k_qkv(const float* __restrict__ Wq, const float* __restrict__ Wk,
           const float* __restrict__ Wv){
    MM_PROLOGUE();
    int bx = blockIdx.x, row0 = blockIdx.y*64;
    const float* B; float* C; int ldb; int colb;
    if (bx < 12)      { B = Wq; C = g_q; ldb = 768; colb = bx*64; }
    else if (bx < 16) { B = Wk; C = g_k; ldb = 256; colb = (bx-12)*64; }
    else              { B = Wv; C = g_v; ldb = 256; colb = (bx-16)*64; }
    mm_async<2,4>(g_xnh, g_xnl, 384, row0, nullptr, nullptr, nullptr, 0,
                  B, ldb, colb, 384, acc);
    epi_f32<4>(C, ldb, row0, colb, 0, acc);
}

__global__ __launch_bounds__(128, 4)
void k_scores(){
    int h = blockIdx.z;
    if (blockIdx.x > blockIdx.y) return;   // fully-masked tile
    MM_PROLOGUE();
    int row0 = blockIdx.y*64, col0 = blockIdx.x*64;
    mm_async<0,4>(g_qh + h*32, g_ql + h*32, 384, row0, nullptr,
                  g_kh + (h/REP)*32, g_kl + (h/REP)*32, 128,
                  nullptr, 0, col0, 32, acc);
    epi_f32<4>(g_scores + (size_t)h*Tt*Tt, Tt, row0, col0, 0, acc);
}

__global__ __launch_bounds__(128, 4)
void k_pv(){
    int h = blockIdx.z;
    MM_PROLOGUE();
    int row0 = blockIdx.y*64;
    mm_async<2,4>(g_sph + (size_t)h*Tt*256, g_spl + (size_t)h*Tt*256, 256, row0, nullptr,
                  nullptr, nullptr, 0,
                  g_v, 256, (h/REP)*64, 256, acc);
    int tid = threadIdx.x, lane = tid & 31, warp = tid >> 5;
    int wm = warp & 1, wn = warp >> 1;
    int gq = lane >> 2, tg = lane & 3;
    #pragma unroll
    for (int mt = 0; mt < 2; mt++){
        int r0 = row0 + wm*32 + mt*16 + gq;
        #pragma unroll
        for (int nt = 0; nt < 4; nt++){
            int wrd = h*32 + wn*16 + nt*4 + tg;
            unsigned hi, lo;
            split_pair(acc[mt][nt][0], acc[mt][nt][1], hi, lo);
            g_ath[(size_t)r0*384 + wrd] = hi; g_atl[(size_t)r0*384 + wrd] = lo;
            split_pair(acc[mt][nt][2], acc[mt][nt][3], hi, lo);
            g_ath[(size_t)(r0+8)*384 + wrd] = hi; g_atl[(size_t)(r0+8)*384 + wrd] = lo;
        }
    }
}

__global__ __launch_bounds__(128, 4)
void k_wo(const float* __restrict__ Wo){
    MM_PROLOGUE();
    int row0 = blockIdx.y*64, col0 = blockIdx.x*64;
    mm_async<2,4>(g_ath, g_atl, 384, row0, nullptr, nullptr, nullptr, 0,
                  Wo, 768, col0, 384, acc);
    epi_f32<4>(g_x, 768, row0, col0, 1, acc);
}

__global__ __launch_bounds__(256, 2)
void k_lmhead(const float* __restrict__ embed, float* __restrict__ logits){
    MM_PROLOGUE();
    int row0 = blockIdx.y*128, col0 = blockIdx.x*64;
    mm_async<1,8>(g_xnh, g_xnl, 384, row0, nullptr, nullptr, nullptr, 0,
                  embed, 768, col0, 384, acc);
    epi_f32<8>(logits, Vv, row0, col0, 0, acc);
}

__global__ __launch_bounds__(128, 4)
void k_moe_up(const float* __restrict__ Wg, const float* __restrict__ Wu){
    int ti = blockIdx.y;
    if (ti >= g_ntiles) return;
    MM_PROLOGUE();
    __shared__ int rowidx[64];
    int e = g_tile_e[ti], base = g_tile_base[ti], rows = g_tile_rows[ti];
    int tid = threadIdx.x;
    if (tid < 64){
        int s = base + (tid < rows ? tid : rows-1);
        rowidx[tid] = g_pairs[s] >> 3;
    }
    __syncthreads();
    int colb = blockIdx.x*64;
    const float* W = (blockIdx.z ? Wu : Wg) + (size_t)e*Hh*Ff;
    mm_async<2,4>(g_xnh, g_xnl, 384, 0, rowidx, nullptr, nullptr, 0,
                  W, Ff, colb, 384, acc);
    float* out = blockIdx.z ? g_actu : g_actg;
    int lane = tid & 31, warp = tid >> 5;
    int wm = warp & 1, wn = warp >> 1;
    int gq = lane >> 2, tg = lane & 3;
    #pragma unroll
    for (int mt = 0; mt < 2; mt++){
        #pragma unroll
        for (int hf = 0; hf < 2; hf++){
            int r = wm*32 + mt*16 + gq + hf*8;
            if (r < rows){
                float* op = &out[(size_t)(base + r)*Ff + colb + wn*32 + tg*2];
                #pragma unroll
                for (int nt = 0; nt < 4; nt++){
                    op[nt*8    ] = acc[mt][nt][hf*2];
                    op[nt*8 + 1] = acc[mt][nt][hf*2 + 1];
                }
            }
        }
    }
}

__global__ void k_act(){
    int i = blockIdx.x*256 + threadIdx.x;   // words
    if (i >= Tt*KK*96) return;
    float g0 = g_actg[2*i], g1 = g_actg[2*i + 1];
    float u0 = g_actu[2*i], u1 = g_actu[2*i + 1];
    float a0 = g0/(1.f+expf(-g0))*u0;
    float a1 = g1/(1.f+expf(-g1))*u1;
    unsigned hi, lo; split_pair(a0, a1, hi, lo);
    g_acth[i] = hi; g_actl[i] = lo;
}

__global__ __launch_bounds__(128, 4)
void k_moe_down(const float* __restrict__ Wd){
    int ti = blockIdx.y;
    if (ti >= g_ntiles) return;
    MM_PROLOGUE();
    __shared__ int rowidx[64];
    int e = g_tile_e[ti], base = g_tile_base[ti], rows = g_tile_rows[ti];
    int tid = threadIdx.x;
    if (tid < 64)
        rowidx[tid] = base + (tid < rows ? tid : rows-1);
    __syncthreads();
    int colb = blockIdx.x*64;
    mm_async<2,4>(g_acth, g_actl, 96, 0, rowidx, nullptr, nullptr, 0,
                  Wd + (size_t)e*Ff*Hh, 768, colb, 96, acc);
    int lane = tid & 31, warp = tid >> 5;
    int wm = warp & 1, wn = warp >> 1;
    int gq = lane >> 2, tg = lane & 3;
    #pragma unroll
    for (int mt = 0; mt < 2; mt++){
        #pragma unroll
        for (int hf = 0; hf < 2; hf++){
            int r = wm*32 + mt*16 + gq + hf*8;
            if (r < rows){
                int pr = g_pairs[base + r];
                float w = g_topw[pr];
                float* op = &g_slotout[(size_t)pr*Hh + colb + wn*32 + tg*2];
                #pragma unroll
                for (int nt = 0; nt < 4; nt++){
                    op[nt*8    ] = w*acc[mt][nt][hf*2];
                    op[nt*8 + 1] = w*acc[mt][nt][hf*2 + 1];
                }
            }
        }
    }
}

// ------------------------------------------------------------------
__global__ void k_embed(const int* __restrict__ ids, const float* __restrict__ emb){
    int t = blockIdx.x;
    int id = ids[t];
    for (int h = threadIdx.x; h < Hh; h += blockDim.x)
        g_x[t*Hh + h] = emb[(size_t)id*Hh + h];
}

__global__ void k_rmsnorm(const float* __restrict__ w){
    int t = blockIdx.x; int tid = threadIdx.x;   // 256
    __shared__ float xs[Hh];
    __shared__ float red[256];
    float s = 0.f;
    #pragma unroll
    for (int c = 0; c < 3; c++){
        float v = g_x[t*Hh + tid + 256*c];
        xs[tid + 256*c] = v; s += v*v;
    }
    red[tid] = s; __syncthreads();
    for (int o = 128; o > 0; o >>= 1){ if (tid < o) red[tid] += red[tid+o]; __syncthreads(); }
    float r = rsqrtf(red[0] / (float)Hh + 1e-6f);
    __syncthreads();
    #pragma unroll
    for (int c = 0; c < 3; c++){
        int h = tid + 256*c;
        xs[h] = xs[h] * r * w[h];
    }
    __syncthreads();
    for (int wd = tid; wd < 384; wd += 256){
        unsigned hi, lo; split_pair(xs[2*wd], xs[2*wd+1], hi, lo);
        g_xnh[t*384 + wd] = hi; g_xnl[t*384 + wd] = lo;
    }
}

__global__ void k_rope2(){
    int t = blockIdx.x;
    int w = threadIdx.x >> 5, j = threadIdx.x & 31;
    const float* p = (w < 12) ? &g_q[t*Hh + w*HDd] : &g_k[t*(NKVv*HDd) + (w-12)*HDd];
    float inv = exp2f(-(float)(2*j) * (13.287712379549449f / 64.0f));
    float ang = (float)t * inv;
    float c = cosf(ang), s = sinf(ang);
    float x0 = p[j], x1 = p[j+32];
    float y0 = x0*c - x1*s;
    float y1 = x1*c + x0*s;
    unsigned full = 0xffffffffu;
    int m = j & 15;
    float sa = __shfl_sync(full, y0, 2*m);
    float sb = __shfl_sync(full, y0, 2*m + 1);
    float ta = __shfl_sync(full, y1, 2*m);
    float tb = __shfl_sync(full, y1, 2*m + 1);
    float f0 = (j < 16) ? sa : ta;
    float f1 = (j < 16) ? sb : tb;
    unsigned hi, lo; split_pair(f0, f1, hi, lo);
    if (w < 12){
        g_qh[t*384 + w*32 + j] = hi; g_ql[t*384 + w*32 + j] = lo;
    } else {
        g_kh[t*128 + (w-12)*32 + j] = hi; g_kl[t*128 + (w-12)*32 + j] = lo;
    }
}

__global__ void k_softmax(){
    int t = blockIdx.x, h = blockIdx.y, tid = threadIdx.x;   // 128 thr
    const float* row = g_scores + (size_t)h*Tt*Tt + (size_t)t*Tt;
    __shared__ float p[Tt];
    __shared__ float red[128];
    float m = -1e30f;
    for (int kk = tid; kk <= t; kk += 128){
        float v = row[kk]*0.125f;
        p[kk] = v; m = fmaxf(m, v);
    }
    red[tid] = m; __syncthreads();
    for (int o = 64; o > 0; o >>= 1){ if (tid < o) red[tid] = fmaxf(red[tid], red[tid+o]); __syncthreads(); }
    m = red[0]; __syncthreads();
    float s = 0.f;
    for (int kk = tid; kk <= t; kk += 128){
        float e = expf(p[kk] - m);
        p[kk] = e; s += e;
    }
    red[tid] = s; __syncthreads();
    for (int o = 64; o > 0; o >>= 1){ if (tid < o) red[tid] += red[tid+o]; __syncthreads(); }
    float inv = 1.0f / red[0];
    size_t obase = ((size_t)h*Tt + t)*256;
    for (int wd = tid; wd < 256; wd += 128){
        float f0 = (2*wd     <= t) ? p[2*wd]*inv     : 0.f;
        float f1 = (2*wd + 1 <= t) ? p[2*wd+1]*inv   : 0.f;
        unsigned hi, lo; split_pair(f0, f1, hi, lo);
        g_sph[obase + wd] = hi; g_spl[obase + wd] = lo;
    }
}

__global__ void k_norm_router(const float* __restrict__ w, const float* __restrict__ rw,
                              int layer){
    int t = blockIdx.x, tid = threadIdx.x;   // 256
    __shared__ float xs[Hh];
    __shared__ float red[256];
    __shared__ float lg[64];
    float loc[3]; float ss = 0.f;
    #pragma unroll
    for (int c = 0; c < 3; c++){
        float v = g_x[t*Hh + tid + 256*c];
        loc[c] = v; ss += v*v;
    }
    red[tid] = ss; __syncthreads();
    for (int o = 128; o > 0; o >>= 1){ if (tid < o) red[tid] += red[tid+o]; __syncthreads(); }
    float r = rsqrtf(red[0] / (float)Hh + 1e-6f);
    #pragma unroll
    for (int c = 0; c < 3; c++){
        int h = tid + 256*c;
        xs[h] = loc[c] * r * w[h];
    }
    __syncthreads();
    for (int wd = tid; wd < 384; wd += 256){
        unsigned hi, lo; split_pair(xs[2*wd], xs[2*wd+1], hi, lo);
        g_xnh[t*384 + wd] = hi; g_xnl[t*384 + wd] = lo;
    }
    if (tid < 64){
        float a0=0.f, a1=0.f, a2=0.f, a3=0.f;
        #pragma unroll 4
        for (int h = 0; h < Hh; h += 4){
            a0 += xs[h  ] * rw[(h  )*Ee + tid];
            a1 += xs[h+1] * rw[(h+1)*Ee + tid];
            a2 += xs[h+2] * rw[(h+2)*Ee + tid];
            a3 += xs[h+3] * rw[(h+3)*Ee + tid];
        }
        lg[tid] = (a0+a1) + (a2+a3);
    }
    __syncthreads();
    if (tid < 32){
        float v0 = lg[tid], v1 = lg[tid+32];
        float m = fmaxf(v0, v1);
        #pragma unroll
        for (int o = 16; o > 0; o >>= 1) m = fmaxf(m, __shfl_xor_sync(0xffffffffu, m, o));
        float e0 = expf(v0 - m), e1 = expf(v1 - m);
        float s = e0 + e1;
        #pragma unroll
        for (int o = 16; o > 0; o >>= 1) s += __shfl_xor_sync(0xffffffffu, s, o);
        float p0 = e0 / s, p1 = e1 / s;
        g_probs[((size_t)layer*Tt + t)*Ee + tid]      = p0;
        g_probs[((size_t)layer*Tt + t)*Ee + tid + 32] = p1;
        lg[tid] = p0; lg[tid+32] = p1;
        __syncwarp();
        float tv[KK]; int ti[KK]; float ws = 0.f;
        #pragma unroll
        for (int k = 0; k < KK; k++){
            float c0 = lg[tid], c1 = lg[tid+32];
            float bv; int bi;
            if (c0 >= c1){ bv = c0; bi = tid; } else { bv = c1; bi = tid+32; }
            #pragma unroll
            for (int o = 16; o > 0; o >>= 1){
                float ov = __shfl_xor_sync(0xffffffffu, bv, o);
                int   oi = __shfl_xor_sync(0xffffffffu, bi, o);
                if (ov > bv || (ov == bv && oi < bi)){ bv = ov; bi = oi; }
            }
            tv[k] = bv; ti[k] = bi; ws += bv;
            if (tid == 0) lg[bi] = -1.0f;
            __syncwarp();
        }
        if (tid == 0){
            float inv = 1.0f / ws;
            #pragma unroll
            for (int k = 0; k < KK; k++){
                g_sel[((size_t)layer*Tt + t)*KK + k] = ti[k];
                g_topw[t*KK + k] = tv[k] * inv;
            }
        }
    }
}

__global__ void k_countscatter(int layer){
    __shared__ int c[Ee], off[Ee+1], fill[Ee];
    int tid = threadIdx.x;   // 512
    if (tid < Ee) c[tid] = 0;
    __syncthreads();
    const int* sel = &g_sel[(size_t)layer*Tt*KK];
    for (int i = tid; i < Tt*KK; i += 512) atomicAdd(&c[sel[i]], 1);
    __syncthreads();
    if (tid == 0){
        int run = 0;
        for (int e = 0; e < Ee; e++){ off[e] = run; run += c[e]; }
        off[Ee] = run;
        int n = 0;
        for (int e = 0; e < Ee; e++){
            for (int b = 0; b < c[e]; b += 64){
                g_tile_e[n] = e;
                g_tile_base[n] = off[e] + b;
                g_tile_rows[n] = min(64, c[e] - b);
                n++;
            }
        }
        g_ntiles = n;
    }
    __syncthreads();
    if (tid < Ee){ g_cnt[tid] = c[tid]; g_off[tid] = off[tid]; fill[tid] = off[tid]; }
    if (tid == 0) g_off[Ee] = off[Ee];
    __syncthreads();
    for (int i = tid; i < Tt*KK; i += 512){
        int e = sel[i];
        int pos = atomicAdd(&fill[e], 1);
        g_pairs[pos] = i;
    }
}

__global__ void k_combine_norm(const float* __restrict__ w){
    int t = blockIdx.x, tid = threadIdx.x;   // 256
    __shared__ float xs[Hh];
    __shared__ float red[256];
    float ss = 0.f;
    #pragma unroll
    for (int c = 0; c < 3; c++){
        int h = tid + 256*c;
        float s = g_x[t*Hh + h];
        #pragma unroll
        for (int sl = 0; sl < KK; sl++)
            s += g_slotout[(size_t)(t*KK + sl)*Hh + h];
        g_x[t*Hh + h] = s;
        xs[h] = s; ss += s*s;
    }
    red[tid] = ss; __syncthreads();
    for (int o = 128; o > 0; o >>= 1){ if (tid < o) red[tid] += red[tid+o]; __syncthreads(); }
    float r = rsqrtf(red[0] / (float)Hh + 1e-6f);
    __syncthreads();
    #pragma unroll
    for (int c = 0; c < 3; c++){
        int h = tid + 256*c;
        xs[h] = xs[h] * r * w[h];
    }
    __syncthreads();
    for (int wd = tid; wd < 384; wd += 256){
        unsigned hi, lo; split_pair(xs[2*wd], xs[2*wd+1], hi, lo);
        g_xnh[t*384 + wd] = hi; g_xnl[t*384 + wd] = lo;
    }
}

__global__ void k_ce(const float* __restrict__ logits, const int* __restrict__ labels){
    int t = blockIdx.x, tid = threadIdx.x;   // 256
    const float* row = logits + (size_t)t*Vv;
    __shared__ float rm[256], rs[256];
    float m = -1e30f, s = 0.f;
    for (int v = tid; v < Vv; v += 256){
        float x = row[v];
        float nm = fmaxf(m, x);
        s = s*expf(m - nm) + expf(x - nm);
        m = nm;
    }
    rm[tid] = m; rs[tid] = s; __syncthreads();
    for (int o = 128; o > 0; o >>= 1){
        if (tid < o){
            float m2 = rm[tid+o], s2 = rs[tid+o];
            float nm = fmaxf(rm[tid], m2);
            rs[tid] = rs[tid]*expf(rm[tid]-nm) + s2*expf(m2-nm);
            rm[tid] = nm;
        }
        __syncthreads();
    }
    if (tid == 0){
        float lse = logf(rs[0]) + rm[0];
        int lbl = labels[t];
        g_nll[t] = (lbl != -100) ? (lse - row[lbl < 0 ? 0 : lbl]) : 0.0f;
    }
}

__global__ void k_final(const int* __restrict__ labels, float* lossp){
    int tid = threadIdx.x;               // 64
    __shared__ int   ccnt[64];
    __shared__ float contrib[64];
    ccnt[tid] = 0; __syncthreads();
    for (int i = tid; i < Ll*Tt*KK; i += 64) atomicAdd(&ccnt[g_sel[i]], 1);
    float sp = 0.f;
    for (int r = 0; r < Ll*Tt; r++) sp += g_probs[(size_t)r*Ee + tid];
    __syncthreads();
    contrib[tid] = sp * (float)ccnt[tid];
    __syncthreads();
    if (tid == 0){
        float aux = 0.f;
        for (int e = 0; e < Ee; e++) aux += contrib[e];
        float NN = (float)(Ll*Tt);
        aux = aux / (NN*NN) * (float)Ee;
        float ce = 0.f; int valid = 0;
        for (int t = 0; t < Tt; t++){ ce += g_nll[t]; if (labels[t] != -100) valid++; }
        ce /= (valid > 0 ? (float)valid : 1.0f);
        if (lossp) *lossp = ce + 0.01f*aux;
    }
}

// ------------------------------------------------------------------
extern "C" void kernel_launch(void* const* d_in, const int* in_sizes, int n_in,
                              void* d_out, int out_size){
    const int*   ids    = (const int*)  d_in[0];
    const int*   labels = (const int*)  d_in[1];
    const float* embed  = (const float*)d_in[2];
    const float* ln1    = (const float*)d_in[3];
    const float* Wq     = (const float*)d_in[4];
    const float* Wk     = (const float*)d_in[5];
    const float* Wv     = (const float*)d_in[6];
    const float* Wo     = (const float*)d_in[7];
    const float* ln2    = (const float*)d_in[8];
    const float* rw     = (const float*)d_in[9];
    const float* Wg     = (const float*)d_in[10];
    const float* Wu     = (const float*)d_in[11];
    const float* Wd     = (const float*)d_in[12];
    const float* fnw    = (const float*)d_in[13];

    float *fbp;
    cudaGetSymbolAddress((void**)&fbp, g_logits_fb);

    float* out = (float*)d_out;
    const size_t TV = (size_t)Tt * Vv;
    float* logits = ((size_t)out_size >= TV) ? out : fbp;
    float* lossp = nullptr;
    if ((size_t)out_size == TV + 1) lossp = out + TV;
    else if (out_size == 1)         lossp = out;

    k_embed<<<Tt, 256>>>(ids, embed);
    k_rmsnorm<<<Tt, 256>>>(ln1);

    for (int i = 0; i < Ll; i++){
        k_qkv<<<dim3(20, Tt/64), 128>>>(Wq + (size_t)i*Hh*NHh*HDd,
                                        Wk + (size_t)i*Hh*NKVv*HDd,
                                        Wv + (size_t)i*Hh*NKVv*HDd);
        k_rope2<<<Tt, 512>>>();
        k_scores<<<dim3(Tt/64, Tt/64, NHh), 128>>>();
        k_softmax<<<dim3(Tt, NHh), 128>>>();
        k_pv<<<dim3(1, Tt/64, NHh), 128>>>();
        k_wo<<<dim3(Hh/64, Tt/64), 128>>>(Wo + (size_t)i*NHh*HDd*Hh);
        k_norm_router<<<Tt, 256>>>(ln2 + (size_t)i*Hh, rw + (size_t)i*Hh*Ee, i);
        k_countscatter<<<1, 512>>>(i);
        k_moe_up<<<dim3(3, MAXTILES, 2), 128>>>(Wg, Wu);
        k_act<<<1536, 256>>>();
        k_moe_down<<<dim3(12, MAXTILES), 128>>>(Wd);
        const float* wnext = (i < Ll-1) ? (ln1 + (size_t)(i+1)*Hh) : fnw;
        k_combine_norm<<<Tt, 256>>>(wnext);
    }

    k_lmhead<<<dim3(Vv/64, Tt/128), 256>>>(embed, logits);
    k_ce<<<Tt, 256>>>(logits, labels);
    k_final<<<1, 64>>>(labels, lossp);
}

// round 10
// speedup vs baseline: 1.6307x; 1.0075x over previous
#include <cuda_runtime.h>
#include <cuda_bf16.h>
#include <math.h>

// ---- model dims ----
#define Tt   512
#define Hh   768
#define Ll   4
#define NHh  12
#define NKVv 4
#define HDd  64
#define Ee   64
#define Ff   192
#define KK   8
#define Vv   32000
#define REP  3   // NH / NKV
#define MAXTILES 128

// ---- fp32 scratch ----
__device__ float g_x[Tt*Hh];
__device__ float g_q[Tt*NHh*HDd];
__device__ float g_k[Tt*NKVv*HDd];
__device__ float g_v[Tt*NKVv*HDd];
__device__ float g_scores[(size_t)NHh*Tt*Tt];
__device__ float g_probs[Ll*Tt*Ee];
__device__ int   g_sel[Ll*Tt*KK];
__device__ float g_topw[Tt*KK];
__device__ int   g_cnt[Ee];
__device__ int   g_off[Ee+1];
__device__ int   g_pairs[Tt*KK];
__device__ int   g_ntiles;
__device__ int   g_tile_e[MAXTILES];
__device__ int   g_tile_base[MAXTILES];
__device__ int   g_tile_rows[MAXTILES];
__device__ float g_actg[Tt*KK*Ff];
__device__ float g_actu[Tt*KK*Ff];
__device__ float g_slotout[Tt*KK*Hh];
__device__ float g_nll[Tt];
__device__ float g_logits_fb[(size_t)Tt*Vv];

// ---- packed bf16 hi/lo word arrays for ACTIVATIONS only ----
__device__ __align__(16) unsigned g_xnh[Tt*384],  g_xnl[Tt*384];
__device__ __align__(16) unsigned g_qh[Tt*384],   g_ql[Tt*384];
__device__ __align__(16) unsigned g_kh[Tt*128],   g_kl[Tt*128];
__device__ __align__(16) unsigned g_sph[(size_t)NHh*Tt*256], g_spl[(size_t)NHh*Tt*256];
__device__ __align__(16) unsigned g_ath[Tt*384],  g_atl[Tt*384];
__device__ __align__(16) unsigned g_acth[Tt*KK*96], g_actl[Tt*KK*96];

// ------------------------------------------------------------------
__device__ __forceinline__ unsigned prmt_hi(unsigned a, unsigned b){
    unsigned d; asm("prmt.b32 %0,%1,%2,0x7632;" : "=r"(d) : "r"(a), "r"(b)); return d;
}
__device__ __forceinline__ unsigned pack_bf16x2(float lo, float hi){
    unsigned d; asm("cvt.rn.bf16x2.f32 %0,%1,%2;" : "=r"(d) : "f"(hi), "f"(lo)); return d;
}
__device__ __forceinline__ void split_pair(float x0, float x1, unsigned &hi, unsigned &lo){
    unsigned u0 = __float_as_uint(x0), u1 = __float_as_uint(x1);
    hi = prmt_hi(u0, u1);
    float r0 = x0 - __uint_as_float(u0 & 0xffff0000u);
    float r1 = x1 - __uint_as_float(u1 & 0xffff0000u);
    lo = pack_bf16x2(r0, r1);
}

#define MMA_BF16(d, a, b) \
    asm volatile("mma.sync.aligned.m16n8k16.row.col.f32.bf16.bf16.f32 " \
                 "{%0,%1,%2,%3},{%4,%5,%6,%7},{%8,%9},{%0,%1,%2,%3};" \
                 : "+f"(d[0]),"+f"(d[1]),"+f"(d[2]),"+f"(d[3]) \
                 : "r"(a[0]),"r"(a[1]),"r"(a[2]),"r"(a[3]),"r"(b[0]),"r"(b[1]))

// cp.async helpers (16B)
__device__ __forceinline__ void cp16(void* s, const void* g){
    unsigned sa = (unsigned)__cvta_generic_to_shared(s);
    asm volatile("cp.async.cg.shared.global [%0], [%1], 16;\n" :: "r"(sa), "l"(g));
}
#define CP_COMMIT() asm volatile("cp.async.commit_group;\n" ::: "memory")
#define CP_WAIT(n)  asm volatile("cp.async.wait_group %0;\n" :: "n"(n) : "memory")

// ------------------------------------------------------------------
// cp.async double-buffered GEMM core. Block tile (NW*16) x 64, NW warps
// (NW/2 along M, 2 along N), warp tile 32x32, k-step = 16 K (8 packed words).
// A: packed hi/lo words [rows, ldaw], rows via rowidx[] or arow0+r.
// B: BMODE 0 = packed [N,Kw] (row base = col0); 1 = fp32 [N,K] rm;
//    2 = fp32 [K,N] rm.  col0 = N-offset (or packed row base for BMODE0).
template<int BMODE, int NW>
__device__ __forceinline__ void mm_async(
    const unsigned* __restrict__ Ah, const unsigned* __restrict__ Al,
    int ldaw, int arow0, const int* __restrict__ rowidx,
    const unsigned* __restrict__ Bph, const unsigned* __restrict__ Bpl, int ldbw,
    const float* __restrict__ Bf, int ldb,
    int col0, int Kw, float acc[2][4][4])
{
    constexpr int MR  = NW*16;
    constexpr int NTH = NW*32;
    __shared__ __align__(16) unsigned As_h[2][MR][12];
    __shared__ __align__(16) unsigned As_l[2][MR][12];
    __shared__ __align__(16) unsigned Bs[2][1536];

    int tid  = threadIdx.x;
    int lane = tid & 31, warp = tid >> 5;
    int wm = warp % (NW/2), wn = warp / (NW/2);
    int gq = lane >> 2, tg = lane & 3;

    int ar = tid >> 1, ac = (tid & 1)*4;
    int gr = rowidx ? rowidx[ar] : (arow0 + ar);
    const unsigned* gAh = Ah + (size_t)gr*ldaw + ac;
    const unsigned* gAl = Al + (size_t)gr*ldaw + ac;

    auto stage = [&](int ks, int buf){
        cp16(&As_h[buf][ar][ac], gAh + ks*8);
        cp16(&As_l[buf][ar][ac], gAl + ks*8);
        #pragma unroll
        for (int it = 0; it < 256/NTH; it++){
            int t2 = tid + it*NTH;
            if (BMODE == 0){
                int a = t2 >> 7, rem = t2 & 127;
                int row = rem >> 1, ch = (rem & 1)*4;
                const unsigned* src = (a ? Bpl : Bph) + (size_t)(col0+row)*ldbw + ks*8 + ch;
                cp16(&Bs[buf][a*768 + row*12 + ch], src);
            } else if (BMODE == 1){
                int row = t2 >> 2, ch = (t2 & 3)*4;
                const float* src = Bf + (size_t)(col0+row)*ldb + ks*16 + ch;
                cp16(&Bs[buf][row*20 + ch], src);
            } else {
                int row = t2 >> 4, ch = (t2 & 15)*4;
                const float* src = Bf + (size_t)(ks*16 + row)*ldb + col0 + ch;
                cp16(&Bs[buf][row*68 + ch], src);
            }
        }
    };

    int nst = Kw >> 3;
    stage(0, 0); CP_COMMIT();

    for (int ks = 0; ks < nst; ks++){
        int buf = ks & 1;
        if (ks + 1 < nst){ stage(ks+1, buf^1); CP_COMMIT(); CP_WAIT(1); }
        else             { CP_WAIT(0); }
        __syncthreads();

        unsigned ah[2][4], al[2][4], bh[4][2], bl[4][2];
        #pragma unroll
        for (int mt = 0; mt < 2; mt++){
            int rb = wm*32 + mt*16 + gq;
            ah[mt][0] = As_h[buf][rb][tg];     ah[mt][1] = As_h[buf][rb+8][tg];
            ah[mt][2] = As_h[buf][rb][tg+4];   ah[mt][3] = As_h[buf][rb+8][tg+4];
            al[mt][0] = As_l[buf][rb][tg];     al[mt][1] = As_l[buf][rb+8][tg];
            al[mt][2] = As_l[buf][rb][tg+4];   al[mt][3] = As_l[buf][rb+8][tg+4];
        }
        #pragma unroll
        for (int nt = 0; nt < 4; nt++){
            int nb = wn*32 + nt*8 + gq;
            if (BMODE == 0){
                bh[nt][0] = Bs[buf][nb*12 + tg];       bh[nt][1] = Bs[buf][nb*12 + tg+4];
                bl[nt][0] = Bs[buf][768 + nb*12 + tg]; bl[nt][1] = Bs[buf][768 + nb*12 + tg+4];
            } else if (BMODE == 1){
                const float* bp = (const float*)Bs[buf];
                float2 v0 = *(const float2*)&bp[nb*20 + 2*tg];
                float2 v1 = *(const float2*)&bp[nb*20 + 2*tg + 8];
                split_pair(v0.x, v0.y, bh[nt][0], bl[nt][0]);
                split_pair(v1.x, v1.y, bh[nt][1], bl[nt][1]);
            } else {
                const float* bp = (const float*)Bs[buf];
                split_pair(bp[(2*tg  )*68 + nb], bp[(2*tg+1)*68 + nb], bh[nt][0], bl[nt][0]);
                split_pair(bp[(2*tg+8)*68 + nb], bp[(2*tg+9)*68 + nb], bh[nt][1], bl[nt][1]);
            }
        }
        #pragma unroll
        for (int mt = 0; mt < 2; mt++)
            #pragma unroll
            for (int nt = 0; nt < 4; nt++){
                MMA_BF16(acc[mt][nt], ah[mt], bh[nt]);
                MMA_BF16(acc[mt][nt], al[mt], bh[nt]);
                MMA_BF16(acc[mt][nt], ah[mt], bl[nt]);
            }
        __syncthreads();
    }
}

#define MM_PROLOGUE() \
    float acc[2][4][4]; \
    _Pragma("unroll") \
    for (int i = 0; i < 2; i++) \
        _Pragma("unroll") \
        for (int j = 0; j < 4; j++) \
            _Pragma("unroll") \
            for (int l = 0; l < 4; l++) acc[i][j][l] = 0.f;

template<int NW>
__device__ __forceinline__ void epi_f32(float* C, int ldc, int row0, int col0,
                                        int doacc, float acc[2][4][4]){
    int tid = threadIdx.x, lane = tid & 31, warp = tid >> 5;
    int wm = warp % (NW/2), wn = warp / (NW/2);
    int gq = lane >> 2, tg = lane & 3;
    #pragma unroll
    for (int mt = 0; mt < 2; mt++){
        int r0 = row0 + wm*32 + mt*16 + gq;
        #pragma unroll
        for (int nt = 0; nt < 4; nt++){
            int c0 = col0 + wn*32 + nt*8 + tg*2;
            float* p0 = &C[(size_t)r0*ldc + c0];
            float* p1 = &C[(size_t)(r0+8)*ldc + c0];
            if (doacc){
                p0[0] += acc[mt][nt][0]; p0[1] += acc[mt][nt][1];
                p1[0] += acc[mt][nt][2]; p1[1] += acc[mt][nt][3];
            } else {
                p0[0] = acc[mt][nt][0]; p0[1] = acc[mt][nt][1];
                p1[0] = acc[mt][nt][2]; p1[1] = acc[mt][nt][3];
            }
        }
    }
}

// ---- GEMM kernels ----
__global__ __launch_bounds__(128, 4)
void k_qkv(const float* __restrict__ Wq, const float* __restrict__ Wk,
           const float* __restrict__ Wv){
    MM_PROLOGUE();
    int bx = blockIdx.x, row0 = blockIdx.y*64;
    const float* B; float* C; int ldb; int colb;
    if (bx < 12)      { B = Wq; C = g_q; ldb = 768; colb = bx*64; }
    else if (bx < 16) { B = Wk; C = g_k; ldb = 256; colb = (bx-12)*64; }
    else              { B = Wv; C = g_v; ldb = 256; colb = (bx-16)*64; }
    mm_async<2,4>(g_xnh, g_xnl, 384, row0, nullptr, nullptr, nullptr, 0,
                  B, ldb, colb, 384, acc);
    epi_f32<4>(C, ldb, row0, colb, 0, acc);
}

__global__ __launch_bounds__(128, 4)
void k_scores(){
    int h = blockIdx.z;
    if (blockIdx.x > blockIdx.y) return;   // fully-masked tile
    MM_PROLOGUE();
    int row0 = blockIdx.y*64, col0 = blockIdx.x*64;
    mm_async<0,4>(g_qh + h*32, g_ql + h*32, 384, row0, nullptr,
                  g_kh + (h/REP)*32, g_kl + (h/REP)*32, 128,
                  nullptr, 0, col0, 32, acc);
    epi_f32<4>(g_scores + (size_t)h*Tt*Tt, Tt, row0, col0, 0, acc);
}

__global__ __launch_bounds__(128, 4)
void k_pv(){
    int h = blockIdx.z;
    MM_PROLOGUE();
    int row0 = blockIdx.y*64;
    mm_async<2,4>(g_sph + (size_t)h*Tt*256, g_spl + (size_t)h*Tt*256, 256, row0, nullptr,
                  nullptr, nullptr, 0,
                  g_v, 256, (h/REP)*64, 256, acc);
    int tid = threadIdx.x, lane = tid & 31, warp = tid >> 5;
    int wm = warp & 1, wn = warp >> 1;
    int gq = lane >> 2, tg = lane & 3;
    #pragma unroll
    for (int mt = 0; mt < 2; mt++){
        int r0 = row0 + wm*32 + mt*16 + gq;
        #pragma unroll
        for (int nt = 0; nt < 4; nt++){
            int wrd = h*32 + wn*16 + nt*4 + tg;
            unsigned hi, lo;
            split_pair(acc[mt][nt][0], acc[mt][nt][1], hi, lo);
            g_ath[(size_t)r0*384 + wrd] = hi; g_atl[(size_t)r0*384 + wrd] = lo;
            split_pair(acc[mt][nt][2], acc[mt][nt][3], hi, lo);
            g_ath[(size_t)(r0+8)*384 + wrd] = hi; g_atl[(size_t)(r0+8)*384 + wrd] = lo;
        }
    }
}

__global__ __launch_bounds__(128, 4)
void k_wo(const float* __restrict__ Wo){
    MM_PROLOGUE();
    int row0 = blockIdx.y*64, col0 = blockIdx.x*64;
    mm_async<2,4>(g_ath, g_atl, 384, row0, nullptr, nullptr, nullptr, 0,
                  Wo, 768, col0, 384, acc);
    epi_f32<4>(g_x, 768, row0, col0, 1, acc);
}

__global__ __launch_bounds__(256, 2)
void k_lmhead(const float* __restrict__ embed, float* __restrict__ logits){
    MM_PROLOGUE();
    int row0 = blockIdx.y*128, col0 = blockIdx.x*64;
    mm_async<1,8>(g_xnh, g_xnl, 384, row0, nullptr, nullptr, nullptr, 0,
                  embed, 768, col0, 384, acc);
    epi_f32<8>(logits, Vv, row0, col0, 0, acc);
}

__global__ __launch_bounds__(128, 4)
void k_moe_up(const float* __restrict__ Wg, const float* __restrict__ Wu){
    int ti = blockIdx.y;
    if (ti >= g_ntiles) return;
    MM_PROLOGUE();
    __shared__ int rowidx[64];
    int e = g_tile_e[ti], base = g_tile_base[ti], rows = g_tile_rows[ti];
    int tid = threadIdx.x;
    if (tid < 64){
        int s = base + (tid < rows ? tid : rows-1);
        rowidx[tid] = g_pairs[s] >> 3;
    }
    __syncthreads();
    int colb = blockIdx.x*64;
    const float* W = (blockIdx.z ? Wu : Wg) + (size_t)e*Hh*Ff;
    mm_async<2,4>(g_xnh, g_xnl, 384, 0, rowidx, nullptr, nullptr, 0,
                  W, Ff, colb, 384, acc);
    float* out = blockIdx.z ? g_actu : g_actg;
    int lane = tid & 31, warp = tid >> 5;
    int wm = warp & 1, wn = warp >> 1;
    int gq = lane >> 2, tg = lane & 3;
    #pragma unroll
    for (int mt = 0; mt < 2; mt++){
        #pragma unroll
        for (int hf = 0; hf < 2; hf++){
            int r = wm*32 + mt*16 + gq + hf*8;
            if (r < rows){
                float* op = &out[(size_t)(base + r)*Ff + colb + wn*32 + tg*2];
                #pragma unroll
                for (int nt = 0; nt < 4; nt++){
                    op[nt*8    ] = acc[mt][nt][hf*2];
                    op[nt*8 + 1] = acc[mt][nt][hf*2 + 1];
                }
            }
        }
    }
}

__global__ void k_act(){
    int i = blockIdx.x*256 + threadIdx.x;   // words
    if (i >= Tt*KK*96) return;
    float g0 = g_actg[2*i], g1 = g_actg[2*i + 1];
    float u0 = g_actu[2*i], u1 = g_actu[2*i + 1];
    float a0 = g0/(1.f+expf(-g0))*u0;
    float a1 = g1/(1.f+expf(-g1))*u1;
    unsigned hi, lo; split_pair(a0, a1, hi, lo);
    g_acth[i] = hi; g_actl[i] = lo;
}

__global__ __launch_bounds__(128, 4)
void k_moe_down(const float* __restrict__ Wd){
    int ti = blockIdx.y;
    if (ti >= g_ntiles) return;
    MM_PROLOGUE();
    __shared__ int rowidx[64];
    int e = g_tile_e[ti], base = g_tile_base[ti], rows = g_tile_rows[ti];
    int tid = threadIdx.x;
    if (tid < 64)
        rowidx[tid] = base + (tid < rows ? tid : rows-1);
    __syncthreads();
    int colb = blockIdx.x*64;
    mm_async<2,4>(g_acth, g_actl, 96, 0, rowidx, nullptr, nullptr, 0,
                  Wd + (size_t)e*Ff*Hh, 768, colb, 96, acc);
    int lane = tid & 31, warp = tid >> 5;
    int wm = warp & 1, wn = warp >> 1;
    int gq = lane >> 2, tg = lane & 3;
    #pragma unroll
    for (int mt = 0; mt < 2; mt++){
        #pragma unroll
        for (int hf = 0; hf < 2; hf++){
            int r = wm*32 + mt*16 + gq + hf*8;
            if (r < rows){
                int pr = g_pairs[base + r];
                float w = g_topw[pr];
                float* op = &g_slotout[(size_t)pr*Hh + colb + wn*32 + tg*2];
                #pragma unroll
                for (int nt = 0; nt < 4; nt++){
                    op[nt*8    ] = w*acc[mt][nt][hf*2];
                    op[nt*8 + 1] = w*acc[mt][nt][hf*2 + 1];
                }
            }
        }
    }
}

// ------------------------------------------------------------------
__global__ void k_embed(const int* __restrict__ ids, const float* __restrict__ emb){
    int t = blockIdx.x;
    int id = ids[t];
    for (int h = threadIdx.x; h < Hh; h += blockDim.x)
        g_x[t*Hh + h] = emb[(size_t)id*Hh + h];
}

__global__ void k_rmsnorm(const float* __restrict__ w){
    int t = blockIdx.x; int tid = threadIdx.x;   // 256
    __shared__ float xs[Hh];
    __shared__ float red[256];
    float s = 0.f;
    #pragma unroll
    for (int c = 0; c < 3; c++){
        float v = g_x[t*Hh + tid + 256*c];
        xs[tid + 256*c] = v; s += v*v;
    }
    red[tid] = s; __syncthreads();
    for (int o = 128; o > 0; o >>= 1){ if (tid < o) red[tid] += red[tid+o]; __syncthreads(); }
    float r = rsqrtf(red[0] / (float)Hh + 1e-6f);
    __syncthreads();
    #pragma unroll
    for (int c = 0; c < 3; c++){
        int h = tid + 256*c;
        xs[h] = xs[h] * r * w[h];
    }
    __syncthreads();
    for (int wd = tid; wd < 384; wd += 256){
        unsigned hi, lo; split_pair(xs[2*wd], xs[2*wd+1], hi, lo);
        g_xnh[t*384 + wd] = hi; g_xnl[t*384 + wd] = lo;
    }
}

__global__ void k_rope2(){
    int t = blockIdx.x;
    int w = threadIdx.x >> 5, j = threadIdx.x & 31;
    const float* p = (w < 12) ? &g_q[t*Hh + w*HDd] : &g_k[t*(NKVv*HDd) + (w-12)*HDd];
    float inv = exp2f(-(float)(2*j) * (13.287712379549449f / 64.0f));
    float ang = (float)t * inv;
    float c = cosf(ang), s = sinf(ang);
    float x0 = p[j], x1 = p[j+32];
    float y0 = x0*c - x1*s;
    float y1 = x1*c + x0*s;
    unsigned full = 0xffffffffu;
    int m = j & 15;
    float sa = __shfl_sync(full, y0, 2*m);
    float sb = __shfl_sync(full, y0, 2*m + 1);
    float ta = __shfl_sync(full, y1, 2*m);
    float tb = __shfl_sync(full, y1, 2*m + 1);
    float f0 = (j < 16) ? sa : ta;
    float f1 = (j < 16) ? sb : tb;
    unsigned hi, lo; split_pair(f0, f1, hi, lo);
    if (w < 12){
        g_qh[t*384 + w*32 + j] = hi; g_ql[t*384 + w*32 + j] = lo;
    } else {
        g_kh[t*128 + (w-12)*32 + j] = hi; g_kl[t*128 + (w-12)*32 + j] = lo;
    }
}

__global__ void k_softmax(){
    int t = blockIdx.x, h = blockIdx.y, tid = threadIdx.x;   // 128 thr
    const float* row = g_scores + (size_t)h*Tt*Tt + (size_t)t*Tt;
    __shared__ float p[Tt];
    __shared__ float red[128];
    float m = -1e30f;
    for (int kk = tid; kk <= t; kk += 128){
        float v = row[kk]*0.125f;
        p[kk] = v; m = fmaxf(m, v);
    }
    red[tid] = m; __syncthreads();
    for (int o = 64; o > 0; o >>= 1){ if (tid < o) red[tid] = fmaxf(red[tid], red[tid+o]); __syncthreads(); }
    m = red[0]; __syncthreads();
    float s = 0.f;
    for (int kk = tid; kk <= t; kk += 128){
        float e = expf(p[kk] - m);
        p[kk] = e; s += e;
    }
    red[tid] = s; __syncthreads();
    for (int o = 64; o > 0; o >>= 1){ if (tid < o) red[tid] += red[tid+o]; __syncthreads(); }
    float inv = 1.0f / red[0];
    size_t obase = ((size_t)h*Tt + t)*256;
    for (int wd = tid; wd < 256; wd += 128){
        float f0 = (2*wd     <= t) ? p[2*wd]*inv     : 0.f;
        float f1 = (2*wd + 1 <= t) ? p[2*wd+1]*inv   : 0.f;
        unsigned hi, lo; split_pair(f0, f1, hi, lo);
        g_sph[obase + wd] = hi; g_spl[obase + wd] = lo;
    }
}

__global__ void k_norm_router(const float* __restrict__ w, const float* __restrict__ rw,
                              int layer){
    int t = blockIdx.x, tid = threadIdx.x;   // 256
    __shared__ float xs[Hh];
    __shared__ float red[256];
    __shared__ float lg[64];
    float loc[3]; float ss = 0.f;
    #pragma unroll
    for (int c = 0; c < 3; c++){
        float v = g_x[t*Hh + tid + 256*c];
        loc[c] = v; ss += v*v;
    }
    red[tid] = ss; __syncthreads();
    for (int o = 128; o > 0; o >>= 1){ if (tid < o) red[tid] += red[tid+o]; __syncthreads(); }
    float r = rsqrtf(red[0] / (float)Hh + 1e-6f);
    #pragma unroll
    for (int c = 0; c < 3; c++){
        int h = tid + 256*c;
        xs[h] = loc[c] * r * w[h];
    }
    __syncthreads();
    for (int wd = tid; wd < 384; wd += 256){
        unsigned hi, lo; split_pair(xs[2*wd], xs[2*wd+1], hi, lo);
        g_xnh[t*384 + wd] = hi; g_xnl[t*384 + wd] = lo;
    }
    if (tid < 64){
        float a0=0.f, a1=0.f, a2=0.f, a3=0.f;
        #pragma unroll 4
        for (int h = 0; h < Hh; h += 4){
            a0 += xs[h  ] * rw[(h  )*Ee + tid];
            a1 += xs[h+1] * rw[(h+1)*Ee + tid];
            a2 += xs[h+2] * rw[(h+2)*Ee + tid];
            a3 += xs[h+3] * rw[(h+3)*Ee + tid];
        }
        lg[tid] = (a0+a1) + (a2+a3);
    }
    __syncthreads();
    if (tid < 32){
        float v0 = lg[tid], v1 = lg[tid+32];
        float m = fmaxf(v0, v1);
        #pragma unroll
        for (int o = 16; o > 0; o >>= 1) m = fmaxf(m, __shfl_xor_sync(0xffffffffu, m, o));
        float e0 = expf(v0 - m), e1 = expf(v1 - m);
        float s = e0 + e1;
        #pragma unroll
        for (int o = 16; o > 0; o >>= 1) s += __shfl_xor_sync(0xffffffffu, s, o);
        float p0 = e0 / s, p1 = e1 / s;
        g_probs[((size_t)layer*Tt + t)*Ee + tid]      = p0;
        g_probs[((size_t)layer*Tt + t)*Ee + tid + 32] = p1;
        lg[tid] = p0; lg[tid+32] = p1;
        __syncwarp();
        float tv[KK]; int ti[KK]; float ws = 0.f;
        #pragma unroll
        for (int k = 0; k < KK; k++){
            float c0 = lg[tid], c1 = lg[tid+32];
            float bv; int bi;
            if (c0 >= c1){ bv = c0; bi = tid; } else { bv = c1; bi = tid+32; }
            #pragma unroll
            for (int o = 16; o > 0; o >>= 1){
                float ov = __shfl_xor_sync(0xffffffffu, bv, o);
                int   oi = __shfl_xor_sync(0xffffffffu, bi, o);
                if (ov > bv || (ov == bv && oi < bi)){ bv = ov; bi = oi; }
            }
            tv[k] = bv; ti[k] = bi; ws += bv;
            if (tid == 0) lg[bi] = -1.0f;
            __syncwarp();
        }
        if (tid == 0){
            float inv = 1.0f / ws;
            #pragma unroll
            for (int k = 0; k < KK; k++){
                g_sel[((size_t)layer*Tt + t)*KK + k] = ti[k];
                g_topw[t*KK + k] = tv[k] * inv;
            }
        }
    }
}

__global__ void k_countscatter(int layer){
    __shared__ int c[Ee], off[Ee+1], fill[Ee];
    int tid = threadIdx.x;   // 512
    if (tid < Ee) c[tid] = 0;
    __syncthreads();
    const int* sel = &g_sel[(size_t)layer*Tt*KK];
    for (int i = tid; i < Tt*KK; i += 512) atomicAdd(&c[sel[i]], 1);
    __syncthreads();
    if (tid == 0){
        int run = 0;
        for (int e = 0; e < Ee; e++){ off[e] = run; run += c[e]; }
        off[Ee] = run;
        int n = 0;
        for (int e = 0; e < Ee; e++){
            for (int b = 0; b < c[e]; b += 64){
                g_tile_e[n] = e;
                g_tile_base[n] = off[e] + b;
                g_tile_rows[n] = min(64, c[e] - b);
                n++;
            }
        }
        g_ntiles = n;
    }
    __syncthreads();
    if (tid < Ee){ g_cnt[tid] = c[tid]; g_off[tid] = off[tid]; fill[tid] = off[tid]; }
    if (tid == 0) g_off[Ee] = off[Ee];
    __syncthreads();
    for (int i = tid; i < Tt*KK; i += 512){
        int e = sel[i];
        int pos = atomicAdd(&fill[e], 1);
        g_pairs[pos] = i;
    }
}

__global__ void k_combine_norm(const float* __restrict__ w){
    int t = blockIdx.x, tid = threadIdx.x;   // 256
    __shared__ float xs[Hh];
    __shared__ float red[256];
    float ss = 0.f;
    #pragma unroll
    for (int c = 0; c < 3; c++){
        int h = tid + 256*c;
        float s = g_x[t*Hh + h];
        #pragma unroll
        for (int sl = 0; sl < KK; sl++)
            s += g_slotout[(size_t)(t*KK + sl)*Hh + h];
        g_x[t*Hh + h] = s;
        xs[h] = s; ss += s*s;
    }
    red[tid] = ss; __syncthreads();
    for (int o = 128; o > 0; o >>= 1){ if (tid < o) red[tid] += red[tid+o]; __syncthreads(); }
    float r = rsqrtf(red[0] / (float)Hh + 1e-6f);
    __syncthreads();
    #pragma unroll
    for (int c = 0; c < 3; c++){
        int h = tid + 256*c;
        xs[h] = xs[h] * r * w[h];
    }
    __syncthreads();
    for (int wd = tid; wd < 384; wd += 256){
        unsigned hi, lo; split_pair(xs[2*wd], xs[2*wd+1], hi, lo);
        g_xnh[t*384 + wd] = hi; g_xnl[t*384 + wd] = lo;
    }
}

__global__ void k_ce(const float* __restrict__ logits, const int* __restrict__ labels){
    int t = blockIdx.x, tid = threadIdx.x;   // 256
    const float* row = logits + (size_t)t*Vv;
    __shared__ float rm[256], rs[256];
    float m = -1e30f, s = 0.f;
    for (int v = tid; v < Vv; v += 256){
        float x = row[v];
        float nm = fmaxf(m, x);
        s = s*expf(m - nm) + expf(x - nm);
        m = nm;
    }
    rm[tid] = m; rs[tid] = s; __syncthreads();
    for (int o = 128; o > 0; o >>= 1){
        if (tid < o){
            float m2 = rm[tid+o], s2 = rs[tid+o];
            float nm = fmaxf(rm[tid], m2);
            rs[tid] = rs[tid]*expf(rm[tid]-nm) + s2*expf(m2-nm);
            rm[tid] = nm;
        }
        __syncthreads();
    }
    if (tid == 0){
        float lse = logf(rs[0]) + rm[0];
        int lbl = labels[t];
        g_nll[t] = (lbl != -100) ? (lse - row[lbl < 0 ? 0 : lbl]) : 0.0f;
    }
}

__global__ void k_final(const int* __restrict__ labels, float* lossp){
    int tid = threadIdx.x;               // 64
    __shared__ int   ccnt[64];
    __shared__ float contrib[64];
    ccnt[tid] = 0; __syncthreads();
    for (int i = tid; i < Ll*Tt*KK; i += 64) atomicAdd(&ccnt[g_sel[i]], 1);
    float sp = 0.f;
    for (int r = 0; r < Ll*Tt; r++) sp += g_probs[(size_t)r*Ee + tid];
    __syncthreads();
    contrib[tid] = sp * (float)ccnt[tid];
    __syncthreads();
    if (tid == 0){
        float aux = 0.f;
        for (int e = 0; e < Ee; e++) aux += contrib[e];
        float NN = (float)(Ll*Tt);
        aux = aux / (NN*NN) * (float)Ee;
        float ce = 0.f; int valid = 0;
        for (int t = 0; t < Tt; t++){ ce += g_nll[t]; if (labels[t] != -100) valid++; }
        ce /= (valid > 0 ? (float)valid : 1.0f);
        if (lossp) *lossp = ce + 0.01f*aux;
    }
}

// ------------------------------------------------------------------
extern "C" void kernel_launch(void* const* d_in, const int* in_sizes, int n_in,
                              void* d_out, int out_size){
    const int*   ids    = (const int*)  d_in[0];
    const int*   labels = (const int*)  d_in[1];
    const float* embed  = (const float*)d_in[2];
    const float* ln1    = (const float*)d_in[3];
    const float* Wq     = (const float*)d_in[4];
    const float* Wk     = (const float*)d_in[5];
    const float* Wv     = (const float*)d_in[6];
    const float* Wo     = (const float*)d_in[7];
    const float* ln2    = (const float*)d_in[8];
    const float* rw     = (const float*)d_in[9];
    const float* Wg     = (const float*)d_in[10];
    const float* Wu     = (const float*)d_in[11];
    const float* Wd     = (const float*)d_in[12];
    const float* fnw    = (const float*)d_in[13];

    float *fbp;
    cudaGetSymbolAddress((void**)&fbp, g_logits_fb);

    float* out = (float*)d_out;
    const size_t TV = (size_t)Tt * Vv;
    float* logits = ((size_t)out_size >= TV) ? out : fbp;
    float* lossp = nullptr;
    if ((size_t)out_size == TV + 1) lossp = out + TV;
    else if (out_size == 1)         lossp = out;

    k_embed<<<Tt, 256>>>(ids, embed);
    k_rmsnorm<<<Tt, 256>>>(ln1);

    for (int i = 0; i < Ll; i++){
        k_qkv<<<dim3(20, Tt/64), 128>>>(Wq + (size_t)i*Hh*NHh*HDd,
                                        Wk + (size_t)i*Hh*NKVv*HDd,
                                        Wv + (size_t)i*Hh*NKVv*HDd);
        k_rope2<<<Tt, 512>>>();
        k_scores<<<dim3(Tt/64, Tt/64, NHh), 128>>>();
        k_softmax<<<dim3(Tt, NHh), 128>>>();
        k_pv<<<dim3(1, Tt/64, NHh), 128>>>();
        k_wo<<<dim3(Hh/64, Tt/64), 128>>>(Wo + (size_t)i*NHh*HDd*Hh);
        k_norm_router<<<Tt, 256>>>(ln2 + (size_t)i*Hh, rw + (size_t)i*Hh*Ee, i);
        k_countscatter<<<1, 512>>>(i);
        k_moe_up<<<dim3(3, MAXTILES, 2), 128>>>(Wg, Wu);
        k_act<<<1536, 256>>>();
        k_moe_down<<<dim3(12, MAXTILES), 128>>>(Wd);
        const float* wnext = (i < Ll-1) ? (ln1 + (size_t)(i+1)*Hh) : fnw;
        k_combine_norm<<<Tt, 256>>>(wnext);
    }

    k_lmhead<<<dim3(Vv/64, Tt/128), 256>>>(embed, logits);
    k_ce<<<Tt, 256>>>(logits, labels);
    k_final<<<1, 64>>>(labels, lossp);
}